// round 1
// baseline (speedup 1.0000x reference)
#include <cuda_runtime.h>

#define BB 4
#define NTOK 32768
#define CC 256
#define HH 8
#define DD 64
#define GG 64
#define INNER 512
#define TOK (BB*NTOK)   // 131072

// ---------------- scratch (device globals; no runtime allocation) ----------------
__device__ float g_fx[TOK*INNER];        // fx_mid, token-major [tok][512]
__device__ float g_w[TOK*INNER];         // slice weights, token-major [tok][h*64+g]
__device__ float g_wsl[CC*INNER];        // folded W_x @ W_slice  [256][512]
__device__ float g_bsl[INNER];           // folded slice bias
__device__ float g_st[BB*HH*GG*DD];      // slice token accumulators
__device__ float g_norm[BB*HH*GG];       // softmax-weight column sums
__device__ float g_os[BB*HH*GG*DD];      // out_slice
__device__ float g_weff[BB*INNER*CC];    // folded out_slice @ W_out, per batch

// ---------------- zero accumulators (must run every graph replay) ----------------
__global__ void k_zero() {
    int i = blockIdx.x * blockDim.x + threadIdx.x;
    if (i < BB*HH*GG*DD) g_st[i] = 0.f;
    if (i < BB*HH*GG)    g_norm[i] = 0.f;
}

// ---------------- fold W_x @ W_slice -> g_wsl, bias -> g_bsl ----------------
__global__ void k_prep(const float* __restrict__ Wx, const float* __restrict__ bx,
                       const float* __restrict__ Wsl, const float* __restrict__ bsl) {
    int c = blockIdx.x;        // 0..255
    int o = threadIdx.x;       // 0..511 (h*64+g)
    int h = o >> 6, gg = o & 63;
    float s = 0.f;
    #pragma unroll 16
    for (int d = 0; d < 64; d++)
        s += Wx[c*INNER + h*64 + d] * Wsl[d*64 + gg];
    g_wsl[c*INNER + o] = s;
    if (c == 0) {
        float t = 0.f;
        #pragma unroll 16
        for (int d = 0; d < 64; d++) t += bx[h*64 + d] * Wsl[d*64 + gg];
        g_bsl[o] = t + bsl[gg];
    }
}

// ---------------- projection: FX = x@W_fx+b, L = x@g_wsl+g_bsl, softmax(L/temp) ----
// tile: 64 tokens x 128 cols (2 heads). grid (TOK/64, 4). 256 threads (16x16), 4x8 regs.
__global__ __launch_bounds__(256) void k_proj(const float* __restrict__ x,
                                              const float* __restrict__ Wfx,
                                              const float* __restrict__ bfx,
                                              const float* __restrict__ temp) {
    __shared__ float xs[64][36];
    __shared__ float wbuf[2][32][132];
    float (*wA)[132] = wbuf[0];
    float (*wB)[132] = wbuf[1];

    int tid = threadIdx.x;
    int tx = tid & 15, ty = tid >> 4;
    int tileM = blockIdx.x, hp = blockIdx.y;
    int row0 = tileM * 64;

    float cfx[4][8], csl[4][8];
    #pragma unroll
    for (int i = 0; i < 4; i++)
        #pragma unroll
        for (int j = 0; j < 8; j++) { cfx[i][j] = 0.f; csl[i][j] = 0.f; }

    int lr = tid >> 3, lc = (tid & 7) * 4;
    int wr = tid >> 5, wc = (tid & 31) * 4;

    for (int k0 = 0; k0 < CC; k0 += 32) {
        *(float4*)&xs[lr][lc]      = *(const float4*)&x[(row0 + lr)      * CC + k0 + lc];
        *(float4*)&xs[lr + 32][lc] = *(const float4*)&x[(row0 + lr + 32) * CC + k0 + lc];
        #pragma unroll
        for (int rr = 0; rr < 4; rr++) {
            int rk = wr + rr * 8;
            *(float4*)&wA[rk][wc] = *(const float4*)&Wfx[(k0 + rk) * INNER + hp * 128 + wc];
            *(float4*)&wB[rk][wc] = *(const float4*)&g_wsl[(k0 + rk) * INNER + hp * 128 + wc];
        }
        __syncthreads();
        #pragma unroll
        for (int k = 0; k < 32; k++) {
            float a[4];
            #pragma unroll
            for (int i = 0; i < 4; i++) a[i] = xs[ty * 4 + i][k];
            #pragma unroll
            for (int j = 0; j < 8; j++) {
                float bA = wA[k][tx + 16 * j];
                float bC = wB[k][tx + 16 * j];
                #pragma unroll
                for (int i = 0; i < 4; i++) { cfx[i][j] += a[i] * bA; csl[i][j] += a[i] * bC; }
            }
        }
        __syncthreads();
    }

    // write FX (+bias)
    #pragma unroll
    for (int i = 0; i < 4; i++) {
        int m = ty * 4 + i;
        #pragma unroll
        for (int j = 0; j < 8; j++) {
            int col = hp * 128 + tx + 16 * j;
            g_fx[(row0 + m) * INNER + col] = cfx[i][j] + bfx[col];
        }
    }

    // logits -> smem (reuse wbuf as 64x132 Ls)
    float* Ls = &wbuf[0][0][0];
    float rt[2];
    rt[0] = 1.0f / fminf(fmaxf(temp[hp * 2 + 0], 0.1f), 5.0f);
    rt[1] = 1.0f / fminf(fmaxf(temp[hp * 2 + 1], 0.1f), 5.0f);
    __syncthreads();
    #pragma unroll
    for (int i = 0; i < 4; i++) {
        int m = ty * 4 + i;
        #pragma unroll
        for (int j = 0; j < 8; j++) {
            int cc = tx + 16 * j;
            Ls[m * 132 + cc] = (csl[i][j] + g_bsl[hp * 128 + cc]) * rt[cc >> 6];
        }
    }
    __syncthreads();

    __shared__ float rsum[128];
    if (tid < 128) {
        int m = tid & 63, hh = tid >> 6;
        float* rowp = &Ls[m * 132 + hh * 64];
        float mx = -1e30f;
        #pragma unroll 16
        for (int g2 = 0; g2 < 64; g2++) mx = fmaxf(mx, rowp[g2]);
        float s = 0.f;
        #pragma unroll 16
        for (int g2 = 0; g2 < 64; g2++) { float e = __expf(rowp[g2] - mx); rowp[g2] = e; s += e; }
        rsum[hh * 64 + m] = 1.0f / s;
    }
    __syncthreads();
    // coalesced weight write
    #pragma unroll
    for (int it = 0; it < 32; it++) {
        int idx = tid + it * 256;
        int m = idx >> 7, cc = idx & 127;
        g_w[(row0 + m) * INNER + hp * 128 + cc] = Ls[m * 132 + cc] * rsum[(cc >> 6) * 64 + m];
    }
}

// ---------------- pooling: ST[bh][g][d] = sum_n w[n][g]*fx[n][d]; norm[g]=sum w ----
// grid (32 bh, 16 n-chunks). 256 threads (16x16), 4x4 regs, split-K atomics.
__global__ __launch_bounds__(256) void k_pool() {
    int bh = blockIdx.x;        // b*8+h
    int chunk = blockIdx.y;     // 0..15
    int b = bh >> 3, h = bh & 7;
    int tid = threadIdx.x;
    int tx = tid & 15, ty = tid >> 4;
    __shared__ float ws[16][68];
    __shared__ float fs[16][68];

    float acc[4][4];
    #pragma unroll
    for (int i = 0; i < 4; i++)
        #pragma unroll
        for (int j = 0; j < 4; j++) acc[i][j] = 0.f;
    float pnorm = 0.f;

    int gl = tid & 63, tt = tid >> 6;
    int t0 = b * NTOK + chunk * (NTOK / 16);

    for (int s = 0; s < (NTOK / 16) / 16; s++) {     // 128 stages of 16 tokens
        #pragma unroll
        for (int t = tt; t < 16; t += 4) {
            int tok = t0 + s * 16 + t;
            float wv = g_w[tok * INNER + h * 64 + gl];
            ws[t][gl] = wv;
            pnorm += wv;
            fs[t][gl] = g_fx[tok * INNER + h * 64 + gl];
        }
        __syncthreads();
        #pragma unroll
        for (int t = 0; t < 16; t++) {
            float4 a  = *(float4*)&ws[t][ty * 4];
            float4 bb = *(float4*)&fs[t][tx * 4];
            acc[0][0] += a.x * bb.x; acc[0][1] += a.x * bb.y; acc[0][2] += a.x * bb.z; acc[0][3] += a.x * bb.w;
            acc[1][0] += a.y * bb.x; acc[1][1] += a.y * bb.y; acc[1][2] += a.y * bb.z; acc[1][3] += a.y * bb.w;
            acc[2][0] += a.z * bb.x; acc[2][1] += a.z * bb.y; acc[2][2] += a.z * bb.z; acc[2][3] += a.z * bb.w;
            acc[3][0] += a.w * bb.x; acc[3][1] += a.w * bb.y; acc[3][2] += a.w * bb.z; acc[3][3] += a.w * bb.w;
        }
        __syncthreads();
    }

    #pragma unroll
    for (int i = 0; i < 4; i++)
        #pragma unroll
        for (int j = 0; j < 4; j++)
            atomicAdd(&g_st[bh * 4096 + (ty * 4 + i) * 64 + tx * 4 + j], acc[i][j]);

    __shared__ float nr[256];
    nr[tid] = pnorm;
    __syncthreads();
    if (tid < 64)
        atomicAdd(&g_norm[bh * 64 + tid], nr[tid] + nr[tid + 64] + nr[tid + 128] + nr[tid + 192]);
}

// ---------------- tiny attention over 64 slice tokens per (b,h) ----------------
__global__ void k_attn(const float* __restrict__ Wq, const float* __restrict__ Wk,
                       const float* __restrict__ Wv) {
    int bh = blockIdx.x;        // 0..31
    int tid = threadIdx.x;      // 256
    __shared__ float sn[64][64];
    __shared__ float ks[64][64];
    __shared__ float nrm[64];

    if (tid < 64) nrm[tid] = g_norm[bh * 64 + tid] + 1e-5f;
    __syncthreads();
    #pragma unroll
    for (int it = 0; it < 16; it++) {
        int idx = tid + it * 256;
        int g2 = idx >> 6;
        sn[g2][idx & 63] = g_st[bh * 4096 + idx] / nrm[g2];
    }
    __syncthreads();
    // K = sn @ Wk (all 256 threads)
    #pragma unroll
    for (int it = 0; it < 16; it++) {
        int idx = tid + it * 256;
        int g2 = idx >> 6, d2 = idx & 63;
        float s0 = 0, s1 = 0, s2 = 0, s3 = 0;
        #pragma unroll
        for (int d = 0; d < 64; d += 4) {
            s0 += sn[g2][d]     * Wk[(d)     * 64 + d2];
            s1 += sn[g2][d + 1] * Wk[(d + 1) * 64 + d2];
            s2 += sn[g2][d + 2] * Wk[(d + 2) * 64 + d2];
            s3 += sn[g2][d + 3] * Wk[(d + 3) * 64 + d2];
        }
        ks[g2][d2] = (s0 + s1) + (s2 + s3);
    }
    __syncthreads();

    float tv[64];
    if (tid < 64) {
        int g2 = tid;
        float q[64];
        #pragma unroll
        for (int d2 = 0; d2 < 64; d2++) {
            float s0 = 0, s1 = 0, s2 = 0, s3 = 0;
            #pragma unroll
            for (int d = 0; d < 64; d += 4) {
                s0 += sn[g2][d]     * Wq[(d)     * 64 + d2];
                s1 += sn[g2][d + 1] * Wq[(d + 1) * 64 + d2];
                s2 += sn[g2][d + 2] * Wq[(d + 2) * 64 + d2];
                s3 += sn[g2][d + 3] * Wq[(d + 3) * 64 + d2];
            }
            q[d2] = (s0 + s1) + (s2 + s3);
        }
        float p[64];
        float mx = -1e30f;
        #pragma unroll
        for (int j = 0; j < 64; j++) {
            float s0 = 0, s1 = 0, s2 = 0, s3 = 0;
            #pragma unroll
            for (int d = 0; d < 64; d += 4) {
                s0 += q[d]     * ks[j][d];
                s1 += q[d + 1] * ks[j][d + 1];
                s2 += q[d + 2] * ks[j][d + 2];
                s3 += q[d + 3] * ks[j][d + 3];
            }
            float s = ((s0 + s1) + (s2 + s3)) * 0.125f;   // DIM_HEAD^-0.5
            p[j] = s;
            mx = fmaxf(mx, s);
        }
        float sum = 0.f;
        #pragma unroll
        for (int j = 0; j < 64; j++) { p[j] = __expf(p[j] - mx); sum += p[j]; }
        float rs = 1.0f / sum;
        // tv = (p @ sn) * rs
        #pragma unroll
        for (int e = 0; e < 64; e++) {
            float s0 = 0, s1 = 0, s2 = 0, s3 = 0;
            #pragma unroll
            for (int j = 0; j < 64; j += 4) {
                s0 += p[j]     * sn[j][e];
                s1 += p[j + 1] * sn[j + 1][e];
                s2 += p[j + 2] * sn[j + 2][e];
                s3 += p[j + 3] * sn[j + 3][e];
            }
            tv[e] = ((s0 + s1) + (s2 + s3)) * rs;
        }
    }
    __syncthreads();               // everyone done reading ks
    if (tid < 64) {
        #pragma unroll
        for (int e = 0; e < 64; e++) ks[tid][e] = tv[e];   // reuse ks as tv storage
    }
    __syncthreads();
    // out_slice = tv @ Wv (all 256 threads)
    #pragma unroll
    for (int it = 0; it < 16; it++) {
        int idx = tid + it * 256;
        int g2 = idx >> 6, d2 = idx & 63;
        float s0 = 0, s1 = 0, s2 = 0, s3 = 0;
        #pragma unroll
        for (int e = 0; e < 64; e += 4) {
            s0 += ks[g2][e]     * Wv[(e)     * 64 + d2];
            s1 += ks[g2][e + 1] * Wv[(e + 1) * 64 + d2];
            s2 += ks[g2][e + 2] * Wv[(e + 2) * 64 + d2];
            s3 += ks[g2][e + 3] * Wv[(e + 3) * 64 + d2];
        }
        g_os[bh * 4096 + idx] = (s0 + s1) + (s2 + s3);
    }
}

// ---------------- fold out_slice into W_out: W_eff[b][h*64+g][c] ----------------
__global__ void k_weff(const float* __restrict__ Wout) {
    int blk = blockIdx.x;           // 0..2047
    int b = blk >> 9;
    int row = blk & 511;            // h*64+g
    int h = row >> 6;
    int tid = threadIdx.x;          // 256 (= c)
    __shared__ float osr[64];
    if (tid < 64) osr[tid] = g_os[(b * 8 + h) * 4096 + (row & 63) * 64 + tid];
    __syncthreads();
    float s = 0.f;
    #pragma unroll 16
    for (int d = 0; d < 64; d++)
        s += osr[d] * Wout[(h * 64 + d) * CC + tid];
    g_weff[b * (INNER * CC) + row * CC + tid] = s;
}

// ---------------- output: y = w @ W_eff[b] + b_out ----------------
// tile 64 tokens x 128 cols, grid (TOK/64, 2), 256 threads, 4x8 regs.
__global__ __launch_bounds__(256) void k_out(const float* __restrict__ bout,
                                             float* __restrict__ y) {
    __shared__ float as_[64][36];
    __shared__ float bs_[32][132];
    int tid = threadIdx.x;
    int tx = tid & 15, ty = tid >> 4;
    int tileM = blockIdx.x, ct = blockIdx.y;
    int row0 = tileM * 64;
    int b = tileM >> 9;   // row0 / NTOK

    float acc[4][8];
    #pragma unroll
    for (int i = 0; i < 4; i++)
        #pragma unroll
        for (int j = 0; j < 8; j++) acc[i][j] = 0.f;

    int lr = tid >> 3, lc = (tid & 7) * 4;
    int wr = tid >> 5, wc = (tid & 31) * 4;

    for (int k0 = 0; k0 < INNER; k0 += 32) {
        *(float4*)&as_[lr][lc]      = *(const float4*)&g_w[(row0 + lr)      * INNER + k0 + lc];
        *(float4*)&as_[lr + 32][lc] = *(const float4*)&g_w[(row0 + lr + 32) * INNER + k0 + lc];
        #pragma unroll
        for (int rr = 0; rr < 4; rr++) {
            int rk = wr + rr * 8;
            *(float4*)&bs_[rk][wc] =
                *(const float4*)&g_weff[b * (INNER * CC) + (k0 + rk) * CC + ct * 128 + wc];
        }
        __syncthreads();
        #pragma unroll
        for (int k = 0; k < 32; k++) {
            float a[4];
            #pragma unroll
            for (int i = 0; i < 4; i++) a[i] = as_[ty * 4 + i][k];
            #pragma unroll
            for (int j = 0; j < 8; j++) {
                float bb = bs_[k][tx + 16 * j];
                #pragma unroll
                for (int i = 0; i < 4; i++) acc[i][j] += a[i] * bb;
            }
        }
        __syncthreads();
    }

    #pragma unroll
    for (int i = 0; i < 4; i++) {
        int m = ty * 4 + i;
        #pragma unroll
        for (int j = 0; j < 8; j++) {
            int col = ct * 128 + tx + 16 * j;
            y[(row0 + m) * CC + col] = acc[i][j] + bout[col];
        }
    }
}

// ---------------- launch ----------------
extern "C" void kernel_launch(void* const* d_in, const int* in_sizes, int n_in,
                              void* d_out, int out_size) {
    const float* x    = (const float*)d_in[0];
    const float* Wfx  = (const float*)d_in[1];
    const float* bfx  = (const float*)d_in[2];
    const float* Wx   = (const float*)d_in[3];
    const float* bx   = (const float*)d_in[4];
    const float* Wsl  = (const float*)d_in[5];
    const float* bsl  = (const float*)d_in[6];
    const float* temp = (const float*)d_in[7];
    const float* Wq   = (const float*)d_in[8];
    const float* Wk   = (const float*)d_in[9];
    const float* Wv   = (const float*)d_in[10];
    const float* Wout = (const float*)d_in[11];
    const float* bout = (const float*)d_in[12];
    float* y = (float*)d_out;

    k_zero<<<512, 256>>>();
    k_prep<<<CC, 512>>>(Wx, bx, Wsl, bsl);
    k_proj<<<dim3(TOK / 64, 4), 256>>>(x, Wfx, bfx, temp);
    k_pool<<<dim3(32, 16), 256>>>();
    k_attn<<<32, 256>>>(Wq, Wk, Wv);
    k_weff<<<2048, 256>>>(Wout);
    k_out<<<dim3(TOK / 64, 2), 256>>>(bout, y);
}

// round 3
// speedup vs baseline: 1.9895x; 1.9895x over previous
#include <cuda_runtime.h>
#include <cuda_bf16.h>
#include <cstdint>

#define BB 4
#define NTOK 32768
#define CC 256
#define HH 8
#define DD 64
#define GG 64
#define INNER 512
#define TOK (BB*NTOK)   // 131072

// ---------------- scratch (device globals; no runtime allocation) ----------------
__device__ __align__(16) float g_fx[(size_t)TOK*INNER];          // fx_mid fp32 [tok][512]
__device__ __align__(16) __nv_bfloat16 g_x_hi[(size_t)TOK*CC];   // x split bf16
__device__ __align__(16) __nv_bfloat16 g_x_lo[(size_t)TOK*CC];
__device__ __align__(16) __nv_bfloat16 g_w_hi[(size_t)TOK*INNER];// slice weights split bf16
__device__ __align__(16) __nv_bfloat16 g_w_lo[(size_t)TOK*INNER];
__device__ __align__(16) __nv_bfloat16 g_wfxT_hi[INNER*CC];      // Wfx^T [n=512][k=256]
__device__ __align__(16) __nv_bfloat16 g_wfxT_lo[INNER*CC];
__device__ __align__(16) __nv_bfloat16 g_wslT_hi[INNER*CC];      // (Wx@Wslice)^T split
__device__ __align__(16) __nv_bfloat16 g_wslT_lo[INNER*CC];
__device__ float g_bsl[INNER];                    // folded slice bias
__device__ float g_st[BB*HH*GG*DD];               // slice token accumulators
__device__ float g_norm[BB*HH*GG];                // weight column sums
__device__ float g_os[BB*HH*GG*DD];               // out_slice
__device__ __align__(16) __nv_bfloat16 g_weffT_hi[BB*CC*INNER];  // W_eff^T [b][n=256][k=512]
__device__ __align__(16) __nv_bfloat16 g_weffT_lo[BB*CC*INNER];

// ============================ helpers ============================
#define DINLINE __device__ __forceinline__

DINLINE uint32_t smem_u32(const void* p) {
    uint32_t a;
    asm("{ .reg .u64 t; cvta.to.shared.u64 t, %1; cvt.u32.u64 %0, t; }" : "=r"(a) : "l"(p));
    return a;
}
DINLINE void cpa16(uint32_t dst, const void* src) {
    asm volatile("cp.async.ca.shared.global [%0], [%1], 16;" :: "r"(dst), "l"(src));
}
#define CP_COMMIT() asm volatile("cp.async.commit_group;" ::: "memory")
#define CP_WAIT1()  asm volatile("cp.async.wait_group 1;" ::: "memory")
#define CP_WAIT0()  asm volatile("cp.async.wait_group 0;" ::: "memory")

DINLINE void ldsm4(uint32_t* r, uint32_t addr) {
    asm volatile("ldmatrix.sync.aligned.m8n8.x4.shared.b16 {%0,%1,%2,%3}, [%4];"
        : "=r"(r[0]), "=r"(r[1]), "=r"(r[2]), "=r"(r[3]) : "r"(addr));
}
DINLINE void mma_bf16(float* d, uint32_t a0, uint32_t a1, uint32_t a2, uint32_t a3,
                      uint32_t b0, uint32_t b1) {
    asm volatile("mma.sync.aligned.m16n8k16.row.col.f32.bf16.bf16.f32 "
        "{%0,%1,%2,%3}, {%4,%5,%6,%7}, {%8,%9}, {%0,%1,%2,%3};"
        : "+f"(d[0]), "+f"(d[1]), "+f"(d[2]), "+f"(d[3])
        : "r"(a0), "r"(a1), "r"(a2), "r"(a3), "r"(b0), "r"(b1));
}
#define SWZ(off) ((off) ^ (((off) >> 3) & 0x70))
#define STG 132   // stage row stride (floats)
#define GSMEM 69632

// ---------------- zero accumulators (must run every graph replay) ----------------
__global__ void k_zero() {
    int i = blockIdx.x * blockDim.x + threadIdx.x;
    if (i < BB*HH*GG*DD) g_st[i] = 0.f;
    if (i < BB*HH*GG)    g_norm[i] = 0.f;
}

// ---------------- split x into bf16 hi/lo ----------------
__global__ void k_split(const float* __restrict__ x) {
    size_t i = (size_t)blockIdx.x * 256 + threadIdx.x;   // one float4 each
    float4 v = ((const float4*)x)[i];
    __nv_bfloat16 hx = __float2bfloat16(v.x), hy = __float2bfloat16(v.y);
    __nv_bfloat16 hz = __float2bfloat16(v.z), hw = __float2bfloat16(v.w);
    __nv_bfloat162 h01, h23, l01, l23;
    h01 = __nv_bfloat162(hx, hy); h23 = __nv_bfloat162(hz, hw);
    l01 = __floats2bfloat162_rn(v.x - __bfloat162float(hx), v.y - __bfloat162float(hy));
    l23 = __floats2bfloat162_rn(v.z - __bfloat162float(hz), v.w - __bfloat162float(hw));
    uint2 uh, ul;
    uh.x = *reinterpret_cast<uint32_t*>(&h01); uh.y = *reinterpret_cast<uint32_t*>(&h23);
    ul.x = *reinterpret_cast<uint32_t*>(&l01); ul.y = *reinterpret_cast<uint32_t*>(&l23);
    ((uint2*)g_x_hi)[i] = uh;
    ((uint2*)g_x_lo)[i] = ul;
}

// ---------------- fold + transpose + bf16-split weights ----------------
__global__ void k_prep(const float* __restrict__ Wx, const float* __restrict__ bx,
                       const float* __restrict__ Wsl, const float* __restrict__ bsl,
                       const float* __restrict__ Wfx) {
    int c = blockIdx.x;        // K index 0..255
    int o = threadIdx.x;       // N index 0..511
    int h = o >> 6, gg = o & 63;
    float s = 0.f;
    #pragma unroll 16
    for (int d = 0; d < 64; d++)
        s += Wx[c*INNER + h*64 + d] * Wsl[d*64 + gg];
    __nv_bfloat16 sh = __float2bfloat16(s);
    g_wslT_hi[o*CC + c] = sh;
    g_wslT_lo[o*CC + c] = __float2bfloat16(s - __bfloat162float(sh));
    float v = Wfx[c*INNER + o];
    __nv_bfloat16 vh = __float2bfloat16(v);
    g_wfxT_hi[o*CC + c] = vh;
    g_wfxT_lo[o*CC + c] = __float2bfloat16(v - __bfloat162float(vh));
    if (c == 0) {
        float t = 0.f;
        #pragma unroll 16
        for (int d = 0; d < 64; d++) t += bx[h*64 + d] * Wsl[d*64 + gg];
        g_bsl[o] = t + bsl[gg];
    }
}

// ---------------- projection GEMM (mma.sync): FX or slice-softmax ----------------
// block M128 x N128, K=256 x 3 segments (12 chunks of 64). grid (1024, 8).
// y<4: FX cols y*128 ; y>=4: logits cols (y-4)*128 (+softmax, writes g_w pair).
__global__ __launch_bounds__(256) void k_proj(const float* __restrict__ bfx,
                                              const float* __restrict__ temp) {
    extern __shared__ char sm[];
    float* stage = (float*)sm;
    uint32_t sb = smem_u32(sm);
    int tid = threadIdx.x;
    int lane = tid & 31, w = tid >> 5;
    int wm = w & 1, wn = w >> 1;
    int tileM = blockIdx.x, yb = blockIdx.y;
    bool isFX = yb < 4;
    int y2 = isFX ? yb : yb - 4;
    int row0 = tileM * 128;
    const __nv_bfloat16* Bhi = isFX ? g_wfxT_hi : g_wslT_hi;
    const __nv_bfloat16* Blo = isFX ? g_wfxT_lo : g_wslT_lo;

    float acc[4][4][4];
    #pragma unroll
    for (int a = 0; a < 4; a++)
        #pragma unroll
        for (int b = 0; b < 4; b++)
            #pragma unroll
            for (int d = 0; d < 4; d++) acc[a][b][d] = 0.f;

    auto issue = [&](int c) {
        int p = c & 1, seg = c >> 2, k0 = (c & 3) * 64;
        const __nv_bfloat16* As = (seg == 2) ? g_x_lo : g_x_hi;
        const __nv_bfloat16* Bs = (seg == 1) ? Blo : Bhi;
        #pragma unroll
        for (int i = 0; i < 4; i++) {
            int id = tid + i * 256, r = id >> 3, c8 = (id & 7) * 8;
            cpa16(sb + p*32768 + SWZ((uint32_t)(r*128 + c8*2)),
                  As + (size_t)(row0 + r) * CC + k0 + c8);
        }
        #pragma unroll
        for (int i = 0; i < 4; i++) {
            int id = tid + i * 256, r = id >> 3, c8 = (id & 7) * 8;
            cpa16(sb + p*32768 + 16384 + SWZ((uint32_t)(r*128 + c8*2)),
                  Bs + (size_t)(y2*128 + r) * CC + k0 + c8);
        }
        CP_COMMIT();
    };

    issue(0);
    for (int c = 0; c < 12; c++) {
        if (c + 1 < 12) { issue(c + 1); CP_WAIT1(); } else { CP_WAIT0(); }
        __syncthreads();
        uint32_t ab = sb + (c & 1) * 32768;
        uint32_t bb = ab + 16384;
        int rA = lane & 15;
        #pragma unroll
        for (int kk = 0; kk < 4; kk++) {
            uint32_t af[4][4], bf[2][4];
            int kc = kk * 16 + (lane >> 4) * 8;
            #pragma unroll
            for (int mi = 0; mi < 4; mi++)
                ldsm4(af[mi], ab + SWZ((uint32_t)((wm*64 + mi*16 + rA)*128 + kc*2)));
            #pragma unroll
            for (int s = 0; s < 2; s++)
                ldsm4(bf[s], bb + SWZ((uint32_t)((wn*32 + s*16 + rA)*128 + kc*2)));
            #pragma unroll
            for (int mi = 0; mi < 4; mi++)
                #pragma unroll
                for (int nj = 0; nj < 4; nj++)
                    mma_bf16(acc[mi][nj], af[mi][0], af[mi][1], af[mi][2], af[mi][3],
                             bf[nj>>1][nj&1], bf[nj>>1][(nj&1)+2]);
        }
        __syncthreads();
    }

    // frags -> stage
    #pragma unroll
    for (int mi = 0; mi < 4; mi++)
        #pragma unroll
        for (int nj = 0; nj < 4; nj++) {
            int row = wm*64 + mi*16 + (lane >> 2);
            int col = wn*32 + nj*8 + (lane & 3)*2;
            *(float2*)&stage[row*STG + col]     = make_float2(acc[mi][nj][0], acc[mi][nj][1]);
            *(float2*)&stage[(row+8)*STG + col] = make_float2(acc[mi][nj][2], acc[mi][nj][3]);
        }
    __syncthreads();

    if (isFX) {
        #pragma unroll
        for (int i = 0; i < 16; i++) {
            int lin = tid + i * 256, r = lin >> 5, c4 = (lin & 31) * 4;
            float4 v = *(float4*)&stage[r*STG + c4];
            float4 bv = *(const float4*)&bfx[y2*128 + c4];
            v.x += bv.x; v.y += bv.y; v.z += bv.z; v.w += bv.w;
            *(float4*)&g_fx[(size_t)(row0 + r)*INNER + y2*128 + c4] = v;
        }
    } else {
        float rt0 = 1.0f / fminf(fmaxf(temp[y2*2 + 0], 0.1f), 5.0f);
        float rt1 = 1.0f / fminf(fmaxf(temp[y2*2 + 1], 0.1f), 5.0f);
        // warp w handles groups w*32 .. w*32+31 (group = row*2 + head)
        for (int gi = 0; gi < 32; gi++) {
            int G = w * 32 + gi;
            int r = G >> 1, hh = G & 1;
            float bb0 = g_bsl[y2*128 + hh*64 + lane];
            float bb1 = g_bsl[y2*128 + hh*64 + 32 + lane];
            float rt = hh ? rt1 : rt0;
            float v0 = (stage[r*STG + hh*64 + lane]      + bb0) * rt;
            float v1 = (stage[r*STG + hh*64 + 32 + lane] + bb1) * rt;
            float m = fmaxf(v0, v1);
            #pragma unroll
            for (int o = 16; o; o >>= 1) m = fmaxf(m, __shfl_xor_sync(0xFFFFFFFFu, m, o));
            float e0 = __expf(v0 - m), e1 = __expf(v1 - m);
            float s = e0 + e1;
            #pragma unroll
            for (int o = 16; o; o >>= 1) s += __shfl_xor_sync(0xFFFFFFFFu, s, o);
            float rs = 1.0f / s;
            stage[r*STG + hh*64 + lane]      = e0 * rs;
            stage[r*STG + hh*64 + 32 + lane] = e1 * rs;
        }
        __syncthreads();
        #pragma unroll
        for (int i = 0; i < 16; i++) {
            int lin = tid + i * 256, r = lin >> 5, c4 = (lin & 31) * 4;
            float4 v = *(float4*)&stage[r*STG + c4];
            __nv_bfloat16 hx = __float2bfloat16(v.x), hy = __float2bfloat16(v.y);
            __nv_bfloat16 hz = __float2bfloat16(v.z), hw = __float2bfloat16(v.w);
            __nv_bfloat162 h01(hx, hy), h23(hz, hw);
            __nv_bfloat162 l01 = __floats2bfloat162_rn(v.x - __bfloat162float(hx),
                                                       v.y - __bfloat162float(hy));
            __nv_bfloat162 l23 = __floats2bfloat162_rn(v.z - __bfloat162float(hz),
                                                       v.w - __bfloat162float(hw));
            uint2 uh, ul;
            uh.x = *reinterpret_cast<uint32_t*>(&h01); uh.y = *reinterpret_cast<uint32_t*>(&h23);
            ul.x = *reinterpret_cast<uint32_t*>(&l01); ul.y = *reinterpret_cast<uint32_t*>(&l23);
            size_t idx = (size_t)(row0 + r)*INNER + y2*128 + c4;
            *(uint2*)&g_w_hi[idx] = uh;
            *(uint2*)&g_w_lo[idx] = ul;
        }
    }
}

// ---------------- pooling: ST[bh][g][d] += w*fx ; norm[g] += w ----------------
__global__ __launch_bounds__(256) void k_pool() {
    int bh = blockIdx.x, chunk = blockIdx.y;
    int b = bh >> 3, h = bh & 7;
    int tid = threadIdx.x;
    int tx = tid & 15, ty = tid >> 4;
    __shared__ float ws[16][68];
    __shared__ float fs[16][68];
    float acc[4][4];
    #pragma unroll
    for (int i = 0; i < 4; i++)
        #pragma unroll
        for (int j = 0; j < 4; j++) acc[i][j] = 0.f;
    float pnorm = 0.f;
    int gl = tid & 63, tt = tid >> 6;
    int t0 = b * NTOK + chunk * (NTOK / 16);
    for (int s = 0; s < (NTOK / 16) / 16; s++) {
        #pragma unroll
        for (int t = tt; t < 16; t += 4) {
            int tok = t0 + s * 16 + t;
            size_t wi = (size_t)tok * INNER + h * 64 + gl;
            float wv = __bfloat162float(g_w_hi[wi]) + __bfloat162float(g_w_lo[wi]);
            ws[t][gl] = wv;
            pnorm += wv;
            fs[t][gl] = g_fx[(size_t)tok * INNER + h * 64 + gl];
        }
        __syncthreads();
        #pragma unroll
        for (int t = 0; t < 16; t++) {
            float4 a  = *(float4*)&ws[t][ty * 4];
            float4 bb = *(float4*)&fs[t][tx * 4];
            acc[0][0] += a.x*bb.x; acc[0][1] += a.x*bb.y; acc[0][2] += a.x*bb.z; acc[0][3] += a.x*bb.w;
            acc[1][0] += a.y*bb.x; acc[1][1] += a.y*bb.y; acc[1][2] += a.y*bb.z; acc[1][3] += a.y*bb.w;
            acc[2][0] += a.z*bb.x; acc[2][1] += a.z*bb.y; acc[2][2] += a.z*bb.z; acc[2][3] += a.z*bb.w;
            acc[3][0] += a.w*bb.x; acc[3][1] += a.w*bb.y; acc[3][2] += a.w*bb.z; acc[3][3] += a.w*bb.w;
        }
        __syncthreads();
    }
    #pragma unroll
    for (int i = 0; i < 4; i++)
        #pragma unroll
        for (int j = 0; j < 4; j++)
            atomicAdd(&g_st[bh * 4096 + (ty*4 + i) * 64 + tx*4 + j], acc[i][j]);
    __shared__ float nr[256];
    nr[tid] = pnorm;
    __syncthreads();
    if (tid < 64)
        atomicAdd(&g_norm[bh * 64 + tid], nr[tid] + nr[tid+64] + nr[tid+128] + nr[tid+192]);
}

// ---------------- tiny attention over slice tokens ----------------
__global__ void k_attn(const float* __restrict__ Wq, const float* __restrict__ Wk,
                       const float* __restrict__ Wv) {
    int bh = blockIdx.x;
    int tid = threadIdx.x;
    __shared__ float sn[64][64];
    __shared__ float ks[64][64];
    __shared__ float nrm[64];
    if (tid < 64) nrm[tid] = g_norm[bh * 64 + tid] + 1e-5f;
    __syncthreads();
    #pragma unroll
    for (int it = 0; it < 16; it++) {
        int idx = tid + it * 256;
        int g2 = idx >> 6;
        sn[g2][idx & 63] = g_st[bh * 4096 + idx] / nrm[g2];
    }
    __syncthreads();
    #pragma unroll
    for (int it = 0; it < 16; it++) {
        int idx = tid + it * 256;
        int g2 = idx >> 6, d2 = idx & 63;
        float s0 = 0, s1 = 0, s2 = 0, s3 = 0;
        #pragma unroll
        for (int d = 0; d < 64; d += 4) {
            s0 += sn[g2][d]   * Wk[(d)   * 64 + d2];
            s1 += sn[g2][d+1] * Wk[(d+1) * 64 + d2];
            s2 += sn[g2][d+2] * Wk[(d+2) * 64 + d2];
            s3 += sn[g2][d+3] * Wk[(d+3) * 64 + d2];
        }
        ks[g2][d2] = (s0 + s1) + (s2 + s3);
    }
    __syncthreads();
    float tv[64];
    if (tid < 64) {
        int g2 = tid;
        float q[64];
        #pragma unroll
        for (int d2 = 0; d2 < 64; d2++) {
            float s0 = 0, s1 = 0, s2 = 0, s3 = 0;
            #pragma unroll
            for (int d = 0; d < 64; d += 4) {
                s0 += sn[g2][d]   * Wq[(d)   * 64 + d2];
                s1 += sn[g2][d+1] * Wq[(d+1) * 64 + d2];
                s2 += sn[g2][d+2] * Wq[(d+2) * 64 + d2];
                s3 += sn[g2][d+3] * Wq[(d+3) * 64 + d2];
            }
            q[d2] = (s0 + s1) + (s2 + s3);
        }
        float p[64];
        float mx = -1e30f;
        #pragma unroll
        for (int j = 0; j < 64; j++) {
            float s0 = 0, s1 = 0, s2 = 0, s3 = 0;
            #pragma unroll
            for (int d = 0; d < 64; d += 4) {
                s0 += q[d]   * ks[j][d];
                s1 += q[d+1] * ks[j][d+1];
                s2 += q[d+2] * ks[j][d+2];
                s3 += q[d+3] * ks[j][d+3];
            }
            float s = ((s0 + s1) + (s2 + s3)) * 0.125f;
            p[j] = s;
            mx = fmaxf(mx, s);
        }
        float sum = 0.f;
        #pragma unroll
        for (int j = 0; j < 64; j++) { p[j] = __expf(p[j] - mx); sum += p[j]; }
        float rs = 1.0f / sum;
        #pragma unroll
        for (int e = 0; e < 64; e++) {
            float s0 = 0, s1 = 0, s2 = 0, s3 = 0;
            #pragma unroll
            for (int j = 0; j < 64; j += 4) {
                s0 += p[j]   * sn[j][e];
                s1 += p[j+1] * sn[j+1][e];
                s2 += p[j+2] * sn[j+2][e];
                s3 += p[j+3] * sn[j+3][e];
            }
            tv[e] = ((s0 + s1) + (s2 + s3)) * rs;
        }
    }
    __syncthreads();
    if (tid < 64) {
        #pragma unroll
        for (int e = 0; e < 64; e++) ks[tid][e] = tv[e];
    }
    __syncthreads();
    #pragma unroll
    for (int it = 0; it < 16; it++) {
        int idx = tid + it * 256;
        int g2 = idx >> 6, d2 = idx & 63;
        float s0 = 0, s1 = 0, s2 = 0, s3 = 0;
        #pragma unroll
        for (int e = 0; e < 64; e += 4) {
            s0 += ks[g2][e]   * Wv[(e)   * 64 + d2];
            s1 += ks[g2][e+1] * Wv[(e+1) * 64 + d2];
            s2 += ks[g2][e+2] * Wv[(e+2) * 64 + d2];
            s3 += ks[g2][e+3] * Wv[(e+3) * 64 + d2];
        }
        g_os[bh * 4096 + idx] = (s0 + s1) + (s2 + s3);
    }
}

// ---------------- fold out_slice into W_out: W_eff^T pair [b][n=256][k=512] ----------------
__global__ void k_weff(const float* __restrict__ Wout) {
    int blk = blockIdx.x;           // b*512 + row
    int b = blk >> 9;
    int row = blk & 511;            // k index: h*64+g
    int h = row >> 6;
    int tid = threadIdx.x;          // n index = c (256)
    __shared__ float osr[64];
    if (tid < 64) osr[tid] = g_os[(b*8 + h) * 4096 + (row & 63) * 64 + tid];
    __syncthreads();
    float s = 0.f;
    #pragma unroll 16
    for (int d = 0; d < 64; d++)
        s += osr[d] * Wout[(h*64 + d) * CC + tid];
    __nv_bfloat16 sh = __float2bfloat16(s);
    size_t idx = (size_t)b * (CC*INNER) + (size_t)tid * INNER + row;
    g_weffT_hi[idx] = sh;
    g_weffT_lo[idx] = __float2bfloat16(s - __bfloat162float(sh));
}

// ---------------- output GEMM (mma.sync): y = w @ W_eff[b] + b_out ----------------
// block M128 x N128, K=512 x 3 segments (24 chunks). grid (1024, 2).
__global__ __launch_bounds__(256) void k_out(const float* __restrict__ bout,
                                             float* __restrict__ y) {
    extern __shared__ char sm[];
    float* stage = (float*)sm;
    uint32_t sb = smem_u32(sm);
    int tid = threadIdx.x;
    int lane = tid & 31, w = tid >> 5;
    int wm = w & 1, wn = w >> 1;
    int tileM = blockIdx.x, ct = blockIdx.y;
    int row0 = tileM * 128;
    int b = tileM >> 8;

    float acc[4][4][4];
    #pragma unroll
    for (int a = 0; a < 4; a++)
        #pragma unroll
        for (int bb2 = 0; bb2 < 4; bb2++)
            #pragma unroll
            for (int d = 0; d < 4; d++) acc[a][bb2][d] = 0.f;

    auto issue = [&](int c) {
        int p = c & 1, seg = c >> 3, k0 = (c & 7) * 64;
        const __nv_bfloat16* As = (seg == 2) ? g_w_lo : g_w_hi;
        const __nv_bfloat16* Bs = (seg == 1) ? g_weffT_lo : g_weffT_hi;
        #pragma unroll
        for (int i = 0; i < 4; i++) {
            int id = tid + i * 256, r = id >> 3, c8 = (id & 7) * 8;
            cpa16(sb + p*32768 + SWZ((uint32_t)(r*128 + c8*2)),
                  As + (size_t)(row0 + r) * INNER + k0 + c8);
        }
        #pragma unroll
        for (int i = 0; i < 4; i++) {
            int id = tid + i * 256, r = id >> 3, c8 = (id & 7) * 8;
            cpa16(sb + p*32768 + 16384 + SWZ((uint32_t)(r*128 + c8*2)),
                  Bs + (size_t)b * (CC*INNER) + (size_t)(ct*128 + r) * INNER + k0 + c8);
        }
        CP_COMMIT();
    };

    issue(0);
    for (int c = 0; c < 24; c++) {
        if (c + 1 < 24) { issue(c + 1); CP_WAIT1(); } else { CP_WAIT0(); }
        __syncthreads();
        uint32_t ab = sb + (c & 1) * 32768;
        uint32_t bbs = ab + 16384;
        int rA = lane & 15;
        #pragma unroll
        for (int kk = 0; kk < 4; kk++) {
            uint32_t af[4][4], bf[2][4];
            int kc = kk * 16 + (lane >> 4) * 8;
            #pragma unroll
            for (int mi = 0; mi < 4; mi++)
                ldsm4(af[mi], ab + SWZ((uint32_t)((wm*64 + mi*16 + rA)*128 + kc*2)));
            #pragma unroll
            for (int s = 0; s < 2; s++)
                ldsm4(bf[s], bbs + SWZ((uint32_t)((wn*32 + s*16 + rA)*128 + kc*2)));
            #pragma unroll
            for (int mi = 0; mi < 4; mi++)
                #pragma unroll
                for (int nj = 0; nj < 4; nj++)
                    mma_bf16(acc[mi][nj], af[mi][0], af[mi][1], af[mi][2], af[mi][3],
                             bf[nj>>1][nj&1], bf[nj>>1][(nj&1)+2]);
        }
        __syncthreads();
    }

    #pragma unroll
    for (int mi = 0; mi < 4; mi++)
        #pragma unroll
        for (int nj = 0; nj < 4; nj++) {
            int row = wm*64 + mi*16 + (lane >> 2);
            int col = wn*32 + nj*8 + (lane & 3)*2;
            *(float2*)&stage[row*STG + col]     = make_float2(acc[mi][nj][0], acc[mi][nj][1]);
            *(float2*)&stage[(row+8)*STG + col] = make_float2(acc[mi][nj][2], acc[mi][nj][3]);
        }
    __syncthreads();
    #pragma unroll
    for (int i = 0; i < 16; i++) {
        int lin = tid + i * 256, r = lin >> 5, c4 = (lin & 31) * 4;
        float4 v = *(float4*)&stage[r*STG + c4];
        float4 bv = *(const float4*)&bout[ct*128 + c4];
        v.x += bv.x; v.y += bv.y; v.z += bv.z; v.w += bv.w;
        *(float4*)&y[(size_t)(row0 + r)*CC + ct*128 + c4] = v;
    }
}

// ---------------- launch ----------------
extern "C" void kernel_launch(void* const* d_in, const int* in_sizes, int n_in,
                              void* d_out, int out_size) {
    const float* x    = (const float*)d_in[0];
    const float* Wfx  = (const float*)d_in[1];
    const float* bfx  = (const float*)d_in[2];
    const float* Wx   = (const float*)d_in[3];
    const float* bx   = (const float*)d_in[4];
    const float* Wsl  = (const float*)d_in[5];
    const float* bsl  = (const float*)d_in[6];
    const float* temp = (const float*)d_in[7];
    const float* Wq   = (const float*)d_in[8];
    const float* Wk   = (const float*)d_in[9];
    const float* Wv   = (const float*)d_in[10];
    const float* Wout = (const float*)d_in[11];
    const float* bout = (const float*)d_in[12];
    float* y = (float*)d_out;

    cudaFuncSetAttribute(k_proj, cudaFuncAttributeMaxDynamicSharedMemorySize, GSMEM);
    cudaFuncSetAttribute(k_out,  cudaFuncAttributeMaxDynamicSharedMemorySize, GSMEM);

    k_zero<<<512, 256>>>();
    k_prep<<<CC, 512>>>(Wx, bx, Wsl, bsl, Wfx);
    k_split<<<(TOK*CC/4)/256, 256>>>(x);
    k_proj<<<dim3(TOK/128, 8), 256, GSMEM>>>(bfx, temp);
    k_pool<<<dim3(32, 16), 256>>>();
    k_attn<<<32, 256>>>(Wq, Wk, Wv);
    k_weff<<<2048, 256>>>(Wout);
    k_out<<<dim3(TOK/128, 2), 256, GSMEM>>>(bout, y);
}

// round 4
// speedup vs baseline: 2.0478x; 1.0293x over previous
#include <cuda_runtime.h>
#include <cuda_bf16.h>
#include <cstdint>

#define BB 4
#define NTOK 32768
#define CC 256
#define HH 8
#define DD 64
#define GG 64
#define INNER 512
#define TOK (BB*NTOK)   // 131072

// ---------------- scratch (device globals; no runtime allocation) ----------------
__device__ __align__(16) float g_fx[(size_t)TOK*INNER];          // fx_mid fp32 [tok][512]
__device__ __align__(16) __nv_bfloat16 g_x_hi[(size_t)TOK*CC];   // x split bf16
__device__ __align__(16) __nv_bfloat16 g_x_lo[(size_t)TOK*CC];
__device__ __align__(16) __nv_bfloat16 g_w_hi[(size_t)TOK*INNER];// slice weights split bf16
__device__ __align__(16) __nv_bfloat16 g_w_lo[(size_t)TOK*INNER];
__device__ __align__(16) __nv_bfloat16 g_wfxT_hi[INNER*CC];      // Wfx^T [n=512][k=256]
__device__ __align__(16) __nv_bfloat16 g_wfxT_lo[INNER*CC];
__device__ __align__(16) __nv_bfloat16 g_wslT_hi[INNER*CC];      // (Wx@Wslice)^T split
__device__ __align__(16) __nv_bfloat16 g_wslT_lo[INNER*CC];
__device__ float g_bsl[INNER];                    // folded slice bias
__device__ float g_st[BB*HH*GG*DD];               // slice token accumulators
__device__ float g_norm[BB*HH*GG];                // weight column sums
__device__ float g_os[BB*HH*GG*DD];               // out_slice
__device__ __align__(16) __nv_bfloat16 g_weffT_hi[BB*CC*INNER];  // W_eff^T [b][n=256][k=512]
__device__ __align__(16) __nv_bfloat16 g_weffT_lo[BB*CC*INNER];

// ============================ helpers ============================
#define DINLINE __device__ __forceinline__

DINLINE uint32_t smem_u32(const void* p) {
    uint32_t a;
    asm("{ .reg .u64 t; cvta.to.shared.u64 t, %1; cvt.u32.u64 %0, t; }" : "=r"(a) : "l"(p));
    return a;
}
DINLINE void cpa16(uint32_t dst, const void* src) {
    asm volatile("cp.async.ca.shared.global [%0], [%1], 16;" :: "r"(dst), "l"(src));
}
#define CP_COMMIT() asm volatile("cp.async.commit_group;" ::: "memory")
#define CP_WAIT1()  asm volatile("cp.async.wait_group 1;" ::: "memory")
#define CP_WAIT0()  asm volatile("cp.async.wait_group 0;" ::: "memory")

DINLINE void ldsm4(uint32_t* r, uint32_t addr) {
    asm volatile("ldmatrix.sync.aligned.m8n8.x4.shared.b16 {%0,%1,%2,%3}, [%4];"
        : "=r"(r[0]), "=r"(r[1]), "=r"(r[2]), "=r"(r[3]) : "r"(addr));
}
DINLINE void mma_bf16(float* d, uint32_t a0, uint32_t a1, uint32_t a2, uint32_t a3,
                      uint32_t b0, uint32_t b1) {
    asm volatile("mma.sync.aligned.m16n8k16.row.col.f32.bf16.bf16.f32 "
        "{%0,%1,%2,%3}, {%4,%5,%6,%7}, {%8,%9}, {%0,%1,%2,%3};"
        : "+f"(d[0]), "+f"(d[1]), "+f"(d[2]), "+f"(d[3])
        : "r"(a0), "r"(a1), "r"(a2), "r"(a3), "r"(b0), "r"(b1));
}
#define SWZ(off) ((off) ^ (((off) >> 3) & 0x70))
#define STG 132   // stage row stride (floats)
#define GSMEM 69632

// ---------------- zero accumulators (must run every graph replay) ----------------
__global__ void k_zero() {
    int i = blockIdx.x * blockDim.x + threadIdx.x;
    if (i < BB*HH*GG*DD) g_st[i] = 0.f;
    if (i < BB*HH*GG)    g_norm[i] = 0.f;
}

// ---------------- split x into bf16 hi/lo ----------------
__global__ void k_split(const float* __restrict__ x) {
    size_t i = (size_t)blockIdx.x * 256 + threadIdx.x;   // one float4 each
    float4 v = ((const float4*)x)[i];
    __nv_bfloat16 hx = __float2bfloat16(v.x), hy = __float2bfloat16(v.y);
    __nv_bfloat16 hz = __float2bfloat16(v.z), hw = __float2bfloat16(v.w);
    __nv_bfloat162 h01, h23, l01, l23;
    h01 = __nv_bfloat162(hx, hy); h23 = __nv_bfloat162(hz, hw);
    l01 = __floats2bfloat162_rn(v.x - __bfloat162float(hx), v.y - __bfloat162float(hy));
    l23 = __floats2bfloat162_rn(v.z - __bfloat162float(hz), v.w - __bfloat162float(hw));
    uint2 uh, ul;
    uh.x = *reinterpret_cast<uint32_t*>(&h01); uh.y = *reinterpret_cast<uint32_t*>(&h23);
    ul.x = *reinterpret_cast<uint32_t*>(&l01); ul.y = *reinterpret_cast<uint32_t*>(&l23);
    ((uint2*)g_x_hi)[i] = uh;
    ((uint2*)g_x_lo)[i] = ul;
}

// ---------------- fold + transpose + bf16-split weights ----------------
__global__ void k_prep(const float* __restrict__ Wx, const float* __restrict__ bx,
                       const float* __restrict__ Wsl, const float* __restrict__ bsl,
                       const float* __restrict__ Wfx) {
    int c = blockIdx.x;        // K index 0..255
    int o = threadIdx.x;       // N index 0..511
    int h = o >> 6, gg = o & 63;
    float s = 0.f;
    #pragma unroll 16
    for (int d = 0; d < 64; d++)
        s += Wx[c*INNER + h*64 + d] * Wsl[d*64 + gg];
    __nv_bfloat16 sh = __float2bfloat16(s);
    g_wslT_hi[o*CC + c] = sh;
    g_wslT_lo[o*CC + c] = __float2bfloat16(s - __bfloat162float(sh));
    float v = Wfx[c*INNER + o];
    __nv_bfloat16 vh = __float2bfloat16(v);
    g_wfxT_hi[o*CC + c] = vh;
    g_wfxT_lo[o*CC + c] = __float2bfloat16(v - __bfloat162float(vh));
    if (c == 0) {
        float t = 0.f;
        #pragma unroll 16
        for (int d = 0; d < 64; d++) t += bx[h*64 + d] * Wsl[d*64 + gg];
        g_bsl[o] = t + bsl[gg];
    }
}

// ---------------- projection GEMM (mma.sync): FX or slice-softmax ----------------
// block M128 x N128, K=256 x 3 segments (12 chunks of 64). grid (8, 1024):
// blockIdx.x = column tile (fast-varying -> A tiles L2-resident), blockIdx.y = tileM.
__global__ __launch_bounds__(256) void k_proj(const float* __restrict__ bfx,
                                              const float* __restrict__ temp) {
    extern __shared__ char sm[];
    float* stage = (float*)sm;
    uint32_t sb = smem_u32(sm);
    int tid = threadIdx.x;
    int lane = tid & 31, w = tid >> 5;
    int wm = w & 1, wn = w >> 1;
    int tileM = blockIdx.y, yb = blockIdx.x;
    bool isFX = yb < 4;
    int y2 = isFX ? yb : yb - 4;
    int row0 = tileM * 128;
    const __nv_bfloat16* Bhi = isFX ? g_wfxT_hi : g_wslT_hi;
    const __nv_bfloat16* Blo = isFX ? g_wfxT_lo : g_wslT_lo;

    float acc[4][4][4];
    #pragma unroll
    for (int a = 0; a < 4; a++)
        #pragma unroll
        for (int b = 0; b < 4; b++)
            #pragma unroll
            for (int d = 0; d < 4; d++) acc[a][b][d] = 0.f;

    auto issue = [&](int c) {
        int p = c & 1, seg = c >> 2, k0 = (c & 3) * 64;
        const __nv_bfloat16* As = (seg == 2) ? g_x_lo : g_x_hi;
        const __nv_bfloat16* Bs = (seg == 1) ? Blo : Bhi;
        #pragma unroll
        for (int i = 0; i < 4; i++) {
            int id = tid + i * 256, r = id >> 3, c8 = (id & 7) * 8;
            cpa16(sb + p*32768 + SWZ((uint32_t)(r*128 + c8*2)),
                  As + (size_t)(row0 + r) * CC + k0 + c8);
        }
        #pragma unroll
        for (int i = 0; i < 4; i++) {
            int id = tid + i * 256, r = id >> 3, c8 = (id & 7) * 8;
            cpa16(sb + p*32768 + 16384 + SWZ((uint32_t)(r*128 + c8*2)),
                  Bs + (size_t)(y2*128 + r) * CC + k0 + c8);
        }
        CP_COMMIT();
    };

    issue(0);
    for (int c = 0; c < 12; c++) {
        if (c + 1 < 12) { issue(c + 1); CP_WAIT1(); } else { CP_WAIT0(); }
        __syncthreads();
        uint32_t ab = sb + (c & 1) * 32768;
        uint32_t bb = ab + 16384;
        int rA = lane & 15;
        #pragma unroll
        for (int kk = 0; kk < 4; kk++) {
            uint32_t af[4][4], bf[2][4];
            int kc = kk * 16 + (lane >> 4) * 8;
            #pragma unroll
            for (int mi = 0; mi < 4; mi++)
                ldsm4(af[mi], ab + SWZ((uint32_t)((wm*64 + mi*16 + rA)*128 + kc*2)));
            #pragma unroll
            for (int s = 0; s < 2; s++)
                ldsm4(bf[s], bb + SWZ((uint32_t)((wn*32 + s*16 + rA)*128 + kc*2)));
            #pragma unroll
            for (int mi = 0; mi < 4; mi++)
                #pragma unroll
                for (int nj = 0; nj < 4; nj++)
                    mma_bf16(acc[mi][nj], af[mi][0], af[mi][1], af[mi][2], af[mi][3],
                             bf[nj>>1][nj&1], bf[nj>>1][(nj&1)+2]);
        }
        __syncthreads();
    }

    // frags -> stage
    #pragma unroll
    for (int mi = 0; mi < 4; mi++)
        #pragma unroll
        for (int nj = 0; nj < 4; nj++) {
            int row = wm*64 + mi*16 + (lane >> 2);
            int col = wn*32 + nj*8 + (lane & 3)*2;
            *(float2*)&stage[row*STG + col]     = make_float2(acc[mi][nj][0], acc[mi][nj][1]);
            *(float2*)&stage[(row+8)*STG + col] = make_float2(acc[mi][nj][2], acc[mi][nj][3]);
        }
    __syncthreads();

    if (isFX) {
        #pragma unroll
        for (int i = 0; i < 16; i++) {
            int lin = tid + i * 256, r = lin >> 5, c4 = (lin & 31) * 4;
            float4 v = *(float4*)&stage[r*STG + c4];
            float4 bv = *(const float4*)&bfx[y2*128 + c4];
            v.x += bv.x; v.y += bv.y; v.z += bv.z; v.w += bv.w;
            *(float4*)&g_fx[(size_t)(row0 + r)*INNER + y2*128 + c4] = v;
        }
    } else {
        float rt0 = 1.0f / fminf(fmaxf(temp[y2*2 + 0], 0.1f), 5.0f);
        float rt1 = 1.0f / fminf(fmaxf(temp[y2*2 + 1], 0.1f), 5.0f);
        // warp w handles groups w*32 .. w*32+31 (group = row*2 + head)
        for (int gi = 0; gi < 32; gi++) {
            int G = w * 32 + gi;
            int r = G >> 1, hh = G & 1;
            float bb0 = g_bsl[y2*128 + hh*64 + lane];
            float bb1 = g_bsl[y2*128 + hh*64 + 32 + lane];
            float rt = hh ? rt1 : rt0;
            float v0 = (stage[r*STG + hh*64 + lane]      + bb0) * rt;
            float v1 = (stage[r*STG + hh*64 + 32 + lane] + bb1) * rt;
            float m = fmaxf(v0, v1);
            #pragma unroll
            for (int o = 16; o; o >>= 1) m = fmaxf(m, __shfl_xor_sync(0xFFFFFFFFu, m, o));
            float e0 = __expf(v0 - m), e1 = __expf(v1 - m);
            float s = e0 + e1;
            #pragma unroll
            for (int o = 16; o; o >>= 1) s += __shfl_xor_sync(0xFFFFFFFFu, s, o);
            float rs = 1.0f / s;
            stage[r*STG + hh*64 + lane]      = e0 * rs;
            stage[r*STG + hh*64 + 32 + lane] = e1 * rs;
        }
        __syncthreads();
        #pragma unroll
        for (int i = 0; i < 16; i++) {
            int lin = tid + i * 256, r = lin >> 5, c4 = (lin & 31) * 4;
            float4 v = *(float4*)&stage[r*STG + c4];
            __nv_bfloat16 hx = __float2bfloat16(v.x), hy = __float2bfloat16(v.y);
            __nv_bfloat16 hz = __float2bfloat16(v.z), hw = __float2bfloat16(v.w);
            __nv_bfloat162 h01(hx, hy), h23(hz, hw);
            __nv_bfloat162 l01 = __floats2bfloat162_rn(v.x - __bfloat162float(hx),
                                                       v.y - __bfloat162float(hy));
            __nv_bfloat162 l23 = __floats2bfloat162_rn(v.z - __bfloat162float(hz),
                                                       v.w - __bfloat162float(hw));
            uint2 uh, ul;
            uh.x = *reinterpret_cast<uint32_t*>(&h01); uh.y = *reinterpret_cast<uint32_t*>(&h23);
            ul.x = *reinterpret_cast<uint32_t*>(&l01); ul.y = *reinterpret_cast<uint32_t*>(&l23);
            size_t idx = (size_t)(row0 + r)*INNER + y2*128 + c4;
            *(uint2*)&g_w_hi[idx] = uh;
            *(uint2*)&g_w_lo[idx] = ul;
        }
    }
}

// ---------------- pooling: ST[bh][g][d] += w*fx ; norm[g] += w ----------------
// 32-token double-buffered stages; fx via cp.async, w prefetched to regs.
__global__ __launch_bounds__(256) void k_pool() {
    int bh = blockIdx.x, chunk = blockIdx.y;
    int b = bh >> 3, h = bh & 7;
    int tid = threadIdx.x;
    int tx = tid & 15, ty = tid >> 4;
    __shared__ float fs[2][32][68];
    __shared__ float ws[2][32][68];
    float acc[4][4];
    #pragma unroll
    for (int i = 0; i < 4; i++)
        #pragma unroll
        for (int j = 0; j < 4; j++) acc[i][j] = 0.f;
    float pnorm = 0.f;

    const int TPC = NTOK / 16;     // 2048 tokens per chunk
    const int NST = TPC / 32;      // 64 stages
    int t0 = b * NTOK + chunk * TPC;
    int fr = tid >> 3, fc = (tid & 7) * 8;
    uint32_t wh[4], wl[4];

    auto loadFX = [&](int s, int p) {
        const float* src = g_fx + (size_t)(t0 + s*32 + fr) * INNER + h*64 + fc;
        cpa16(smem_u32(&fs[p][fr][fc]),     src);
        cpa16(smem_u32(&fs[p][fr][fc + 4]), src + 4);
        CP_COMMIT();
    };
    auto loadW = [&](int s) {
        #pragma unroll
        for (int i = 0; i < 4; i++) {
            int pid = tid + i * 256;
            int wr = pid >> 5, wg = (pid & 31) * 2;
            size_t idx = (size_t)(t0 + s*32 + wr) * INNER + h*64 + wg;
            wh[i] = *(const uint32_t*)&g_w_hi[idx];
            wl[i] = *(const uint32_t*)&g_w_lo[idx];
        }
    };
    auto storeW = [&](int p) {
        #pragma unroll
        for (int i = 0; i < 4; i++) {
            int pid = tid + i * 256;
            int wr = pid >> 5, wg = (pid & 31) * 2;
            float2 hv = __bfloat1622float2(*(__nv_bfloat162*)&wh[i]);
            float2 lv = __bfloat1622float2(*(__nv_bfloat162*)&wl[i]);
            float v0 = hv.x + lv.x, v1 = hv.y + lv.y;
            ws[p][wr][wg] = v0; ws[p][wr][wg + 1] = v1;
            pnorm += v0 + v1;
        }
    };

    loadW(0);
    loadFX(0, 0);
    storeW(0);
    for (int s = 0; s < NST; s++) {
        int p = s & 1;
        if (s + 1 < NST) { loadW(s + 1); loadFX(s + 1, 1 - p); CP_WAIT1(); }
        else CP_WAIT0();
        __syncthreads();
        #pragma unroll 8
        for (int t = 0; t < 32; t++) {
            float4 a  = *(float4*)&ws[p][t][ty * 4];
            float4 bb = *(float4*)&fs[p][t][tx * 4];
            acc[0][0] += a.x*bb.x; acc[0][1] += a.x*bb.y; acc[0][2] += a.x*bb.z; acc[0][3] += a.x*bb.w;
            acc[1][0] += a.y*bb.x; acc[1][1] += a.y*bb.y; acc[1][2] += a.y*bb.z; acc[1][3] += a.y*bb.w;
            acc[2][0] += a.z*bb.x; acc[2][1] += a.z*bb.y; acc[2][2] += a.z*bb.z; acc[2][3] += a.z*bb.w;
            acc[3][0] += a.w*bb.x; acc[3][1] += a.w*bb.y; acc[3][2] += a.w*bb.z; acc[3][3] += a.w*bb.w;
        }
        __syncthreads();
        if (s + 1 < NST) storeW(1 - p);
    }
    #pragma unroll
    for (int i = 0; i < 4; i++)
        #pragma unroll
        for (int j = 0; j < 4; j++)
            atomicAdd(&g_st[bh * 4096 + (ty*4 + i) * 64 + tx*4 + j], acc[i][j]);
    __shared__ float nr[256];
    nr[tid] = pnorm;
    __syncthreads();
    if (tid < 64)
        atomicAdd(&g_norm[bh * 64 + tid], nr[tid] + nr[tid+64] + nr[tid+128] + nr[tid+192]);
}

// ---------------- tiny attention over slice tokens ----------------
__global__ void k_attn(const float* __restrict__ Wq, const float* __restrict__ Wk,
                       const float* __restrict__ Wv) {
    int bh = blockIdx.x;
    int tid = threadIdx.x;
    __shared__ float sn[64][64];
    __shared__ float ks[64][64];
    __shared__ float nrm[64];
    if (tid < 64) nrm[tid] = g_norm[bh * 64 + tid] + 1e-5f;
    __syncthreads();
    #pragma unroll
    for (int it = 0; it < 16; it++) {
        int idx = tid + it * 256;
        int g2 = idx >> 6;
        sn[g2][idx & 63] = g_st[bh * 4096 + idx] / nrm[g2];
    }
    __syncthreads();
    #pragma unroll
    for (int it = 0; it < 16; it++) {
        int idx = tid + it * 256;
        int g2 = idx >> 6, d2 = idx & 63;
        float s0 = 0, s1 = 0, s2 = 0, s3 = 0;
        #pragma unroll
        for (int d = 0; d < 64; d += 4) {
            s0 += sn[g2][d]   * Wk[(d)   * 64 + d2];
            s1 += sn[g2][d+1] * Wk[(d+1) * 64 + d2];
            s2 += sn[g2][d+2] * Wk[(d+2) * 64 + d2];
            s3 += sn[g2][d+3] * Wk[(d+3) * 64 + d2];
        }
        ks[g2][d2] = (s0 + s1) + (s2 + s3);
    }
    __syncthreads();
    float tv[64];
    if (tid < 64) {
        int g2 = tid;
        float q[64];
        #pragma unroll
        for (int d2 = 0; d2 < 64; d2++) {
            float s0 = 0, s1 = 0, s2 = 0, s3 = 0;
            #pragma unroll
            for (int d = 0; d < 64; d += 4) {
                s0 += sn[g2][d]   * Wq[(d)   * 64 + d2];
                s1 += sn[g2][d+1] * Wq[(d+1) * 64 + d2];
                s2 += sn[g2][d+2] * Wq[(d+2) * 64 + d2];
                s3 += sn[g2][d+3] * Wq[(d+3) * 64 + d2];
            }
            q[d2] = (s0 + s1) + (s2 + s3);
        }
        float p[64];
        float mx = -1e30f;
        #pragma unroll
        for (int j = 0; j < 64; j++) {
            float s0 = 0, s1 = 0, s2 = 0, s3 = 0;
            #pragma unroll
            for (int d = 0; d < 64; d += 4) {
                s0 += q[d]   * ks[j][d];
                s1 += q[d+1] * ks[j][d+1];
                s2 += q[d+2] * ks[j][d+2];
                s3 += q[d+3] * ks[j][d+3];
            }
            float s = ((s0 + s1) + (s2 + s3)) * 0.125f;
            p[j] = s;
            mx = fmaxf(mx, s);
        }
        float sum = 0.f;
        #pragma unroll
        for (int j = 0; j < 64; j++) { p[j] = __expf(p[j] - mx); sum += p[j]; }
        float rs = 1.0f / sum;
        #pragma unroll
        for (int e = 0; e < 64; e++) {
            float s0 = 0, s1 = 0, s2 = 0, s3 = 0;
            #pragma unroll
            for (int j = 0; j < 64; j += 4) {
                s0 += p[j]   * sn[j][e];
                s1 += p[j+1] * sn[j+1][e];
                s2 += p[j+2] * sn[j+2][e];
                s3 += p[j+3] * sn[j+3][e];
            }
            tv[e] = ((s0 + s1) + (s2 + s3)) * rs;
        }
    }
    __syncthreads();
    if (tid < 64) {
        #pragma unroll
        for (int e = 0; e < 64; e++) ks[tid][e] = tv[e];
    }
    __syncthreads();
    #pragma unroll
    for (int it = 0; it < 16; it++) {
        int idx = tid + it * 256;
        int g2 = idx >> 6, d2 = idx & 63;
        float s0 = 0, s1 = 0, s2 = 0, s3 = 0;
        #pragma unroll
        for (int e = 0; e < 64; e += 4) {
            s0 += ks[g2][e]   * Wv[(e)   * 64 + d2];
            s1 += ks[g2][e+1] * Wv[(e+1) * 64 + d2];
            s2 += ks[g2][e+2] * Wv[(e+2) * 64 + d2];
            s3 += ks[g2][e+3] * Wv[(e+3) * 64 + d2];
        }
        g_os[bh * 4096 + idx] = (s0 + s1) + (s2 + s3);
    }
}

// ---------------- fold out_slice into W_out: W_eff^T pair [b][n=256][k=512] ----------------
__global__ void k_weff(const float* __restrict__ Wout) {
    int blk = blockIdx.x;           // b*512 + row
    int b = blk >> 9;
    int row = blk & 511;            // k index: h*64+g
    int h = row >> 6;
    int tid = threadIdx.x;          // n index = c (256)
    __shared__ float osr[64];
    if (tid < 64) osr[tid] = g_os[(b*8 + h) * 4096 + (row & 63) * 64 + tid];
    __syncthreads();
    float s = 0.f;
    #pragma unroll 16
    for (int d = 0; d < 64; d++)
        s += osr[d] * Wout[(h*64 + d) * CC + tid];
    __nv_bfloat16 sh = __float2bfloat16(s);
    size_t idx = (size_t)b * (CC*INNER) + (size_t)tid * INNER + row;
    g_weffT_hi[idx] = sh;
    g_weffT_lo[idx] = __float2bfloat16(s - __bfloat162float(sh));
}

// ---------------- output GEMM (mma.sync): y = w @ W_eff[b] + b_out ----------------
// block M128 x N128, K=512 x 3 segments (24 chunks). grid (2, 1024): ct fast-varying.
__global__ __launch_bounds__(256) void k_out(const float* __restrict__ bout,
                                             float* __restrict__ y) {
    extern __shared__ char sm[];
    float* stage = (float*)sm;
    uint32_t sb = smem_u32(sm);
    int tid = threadIdx.x;
    int lane = tid & 31, w = tid >> 5;
    int wm = w & 1, wn = w >> 1;
    int tileM = blockIdx.y, ct = blockIdx.x;
    int row0 = tileM * 128;
    int b = tileM >> 8;

    float acc[4][4][4];
    #pragma unroll
    for (int a = 0; a < 4; a++)
        #pragma unroll
        for (int bb2 = 0; bb2 < 4; bb2++)
            #pragma unroll
            for (int d = 0; d < 4; d++) acc[a][bb2][d] = 0.f;

    auto issue = [&](int c) {
        int p = c & 1, seg = c >> 3, k0 = (c & 7) * 64;
        const __nv_bfloat16* As = (seg == 2) ? g_w_lo : g_w_hi;
        const __nv_bfloat16* Bs = (seg == 1) ? g_weffT_lo : g_weffT_hi;
        #pragma unroll
        for (int i = 0; i < 4; i++) {
            int id = tid + i * 256, r = id >> 3, c8 = (id & 7) * 8;
            cpa16(sb + p*32768 + SWZ((uint32_t)(r*128 + c8*2)),
                  As + (size_t)(row0 + r) * INNER + k0 + c8);
        }
        #pragma unroll
        for (int i = 0; i < 4; i++) {
            int id = tid + i * 256, r = id >> 3, c8 = (id & 7) * 8;
            cpa16(sb + p*32768 + 16384 + SWZ((uint32_t)(r*128 + c8*2)),
                  Bs + (size_t)b * (CC*INNER) + (size_t)(ct*128 + r) * INNER + k0 + c8);
        }
        CP_COMMIT();
    };

    issue(0);
    for (int c = 0; c < 24; c++) {
        if (c + 1 < 24) { issue(c + 1); CP_WAIT1(); } else { CP_WAIT0(); }
        __syncthreads();
        uint32_t ab = sb + (c & 1) * 32768;
        uint32_t bbs = ab + 16384;
        int rA = lane & 15;
        #pragma unroll
        for (int kk = 0; kk < 4; kk++) {
            uint32_t af[4][4], bf[2][4];
            int kc = kk * 16 + (lane >> 4) * 8;
            #pragma unroll
            for (int mi = 0; mi < 4; mi++)
                ldsm4(af[mi], ab + SWZ((uint32_t)((wm*64 + mi*16 + rA)*128 + kc*2)));
            #pragma unroll
            for (int s = 0; s < 2; s++)
                ldsm4(bf[s], bbs + SWZ((uint32_t)((wn*32 + s*16 + rA)*128 + kc*2)));
            #pragma unroll
            for (int mi = 0; mi < 4; mi++)
                #pragma unroll
                for (int nj = 0; nj < 4; nj++)
                    mma_bf16(acc[mi][nj], af[mi][0], af[mi][1], af[mi][2], af[mi][3],
                             bf[nj>>1][nj&1], bf[nj>>1][(nj&1)+2]);
        }
        __syncthreads();
    }

    #pragma unroll
    for (int mi = 0; mi < 4; mi++)
        #pragma unroll
        for (int nj = 0; nj < 4; nj++) {
            int row = wm*64 + mi*16 + (lane >> 2);
            int col = wn*32 + nj*8 + (lane & 3)*2;
            *(float2*)&stage[row*STG + col]     = make_float2(acc[mi][nj][0], acc[mi][nj][1]);
            *(float2*)&stage[(row+8)*STG + col] = make_float2(acc[mi][nj][2], acc[mi][nj][3]);
        }
    __syncthreads();
    #pragma unroll
    for (int i = 0; i < 16; i++) {
        int lin = tid + i * 256, r = lin >> 5, c4 = (lin & 31) * 4;
        float4 v = *(float4*)&stage[r*STG + c4];
        float4 bv = *(const float4*)&bout[ct*128 + c4];
        v.x += bv.x; v.y += bv.y; v.z += bv.z; v.w += bv.w;
        *(float4*)&y[(size_t)(row0 + r)*CC + ct*128 + c4] = v;
    }
}

// ---------------- launch ----------------
extern "C" void kernel_launch(void* const* d_in, const int* in_sizes, int n_in,
                              void* d_out, int out_size) {
    const float* x    = (const float*)d_in[0];
    const float* Wfx  = (const float*)d_in[1];
    const float* bfx  = (const float*)d_in[2];
    const float* Wx   = (const float*)d_in[3];
    const float* bx   = (const float*)d_in[4];
    const float* Wsl  = (const float*)d_in[5];
    const float* bsl  = (const float*)d_in[6];
    const float* temp = (const float*)d_in[7];
    const float* Wq   = (const float*)d_in[8];
    const float* Wk   = (const float*)d_in[9];
    const float* Wv   = (const float*)d_in[10];
    const float* Wout = (const float*)d_in[11];
    const float* bout = (const float*)d_in[12];
    float* y = (float*)d_out;

    cudaFuncSetAttribute(k_proj, cudaFuncAttributeMaxDynamicSharedMemorySize, GSMEM);
    cudaFuncSetAttribute(k_out,  cudaFuncAttributeMaxDynamicSharedMemorySize, GSMEM);

    k_zero<<<512, 256>>>();
    k_prep<<<CC, 512>>>(Wx, bx, Wsl, bsl, Wfx);
    k_split<<<(TOK*CC/4)/256, 256>>>(x);
    k_proj<<<dim3(8, TOK/128), 256, GSMEM>>>(bfx, temp);
    k_pool<<<dim3(32, 16), 256>>>();
    k_attn<<<32, 256>>>(Wq, Wk, Wv);
    k_weff<<<2048, 256>>>(Wout);
    k_out<<<dim3(2, TOK/128), 256, GSMEM>>>(bout, y);
}

// round 5
// speedup vs baseline: 2.1121x; 1.0314x over previous
#include <cuda_runtime.h>
#include <cuda_bf16.h>
#include <cstdint>

#define BB 4
#define NTOK 32768
#define CC 256
#define HH 8
#define DD 64
#define GG 64
#define INNER 512
#define TOK (BB*NTOK)   // 131072

// ---------------- scratch (device globals; no runtime allocation) ----------------
__device__ __align__(16) float g_fx[(size_t)TOK*INNER];          // fx_mid fp32 [tok][512]
__device__ __align__(16) __nv_bfloat16 g_x_hi[(size_t)TOK*CC];   // x split bf16
__device__ __align__(16) __nv_bfloat16 g_x_lo[(size_t)TOK*CC];
__device__ __align__(16) __nv_bfloat16 g_w_hi[(size_t)TOK*INNER];// slice weights split bf16
__device__ __align__(16) __nv_bfloat16 g_w_lo[(size_t)TOK*INNER];
__device__ __align__(16) __nv_bfloat16 g_wfxT_hi[INNER*CC];      // Wfx^T [n=512][k=256]
__device__ __align__(16) __nv_bfloat16 g_wfxT_lo[INNER*CC];
__device__ __align__(16) __nv_bfloat16 g_wslT_hi[INNER*CC];      // (Wx@Wslice)^T split
__device__ __align__(16) __nv_bfloat16 g_wslT_lo[INNER*CC];
__device__ float g_bsl[INNER];                    // folded slice bias
__device__ float g_st[BB*HH*GG*DD];               // slice token accumulators
__device__ float g_norm[BB*HH*GG];                // weight column sums
__device__ float g_os[BB*HH*GG*DD];               // out_slice
__device__ __align__(16) __nv_bfloat16 g_weffT_hi[BB*CC*INNER];  // W_eff^T [b][n=256][k=512]
__device__ __align__(16) __nv_bfloat16 g_weffT_lo[BB*CC*INNER];

// ============================ helpers ============================
#define DINLINE __device__ __forceinline__

DINLINE uint32_t smem_u32(const void* p) {
    uint32_t a;
    asm("{ .reg .u64 t; cvta.to.shared.u64 t, %1; cvt.u32.u64 %0, t; }" : "=r"(a) : "l"(p));
    return a;
}
DINLINE void cpa16(uint32_t dst, const void* src) {
    asm volatile("cp.async.ca.shared.global [%0], [%1], 16;" :: "r"(dst), "l"(src));
}
#define CP_COMMIT() asm volatile("cp.async.commit_group;" ::: "memory")
#define CP_WAIT1()  asm volatile("cp.async.wait_group 1;" ::: "memory")
#define CP_WAIT0()  asm volatile("cp.async.wait_group 0;" ::: "memory")

DINLINE void ldsm4(uint32_t* r, uint32_t addr) {
    asm volatile("ldmatrix.sync.aligned.m8n8.x4.shared.b16 {%0,%1,%2,%3}, [%4];"
        : "=r"(r[0]), "=r"(r[1]), "=r"(r[2]), "=r"(r[3]) : "r"(addr));
}
DINLINE void mma_bf16(float* d, uint32_t a0, uint32_t a1, uint32_t a2, uint32_t a3,
                      uint32_t b0, uint32_t b1) {
    asm volatile("mma.sync.aligned.m16n8k16.row.col.f32.bf16.bf16.f32 "
        "{%0,%1,%2,%3}, {%4,%5,%6,%7}, {%8,%9}, {%0,%1,%2,%3};"
        : "+f"(d[0]), "+f"(d[1]), "+f"(d[2]), "+f"(d[3])
        : "r"(a0), "r"(a1), "r"(a2), "r"(a3), "r"(b0), "r"(b1));
}
#define SWZ(off) ((off) ^ (((off) >> 3) & 0x70))
#define STG 132   // stage row stride (floats)
#define GSMEM 98304   // 3 stages x (16KB A + 16KB B); fp32 stage aliases bytes [0,67584)

// ---------------- zero accumulators (must run every graph replay) ----------------
__global__ void k_zero() {
    int i = blockIdx.x * blockDim.x + threadIdx.x;
    if (i < BB*HH*GG*DD) g_st[i] = 0.f;
    if (i < BB*HH*GG)    g_norm[i] = 0.f;
}

// ---------------- split x into bf16 hi/lo ----------------
__global__ void k_split(const float* __restrict__ x) {
    size_t i = (size_t)blockIdx.x * 256 + threadIdx.x;   // one float4 each
    float4 v = ((const float4*)x)[i];
    __nv_bfloat16 hx = __float2bfloat16(v.x), hy = __float2bfloat16(v.y);
    __nv_bfloat16 hz = __float2bfloat16(v.z), hw = __float2bfloat16(v.w);
    __nv_bfloat162 h01, h23, l01, l23;
    h01 = __nv_bfloat162(hx, hy); h23 = __nv_bfloat162(hz, hw);
    l01 = __floats2bfloat162_rn(v.x - __bfloat162float(hx), v.y - __bfloat162float(hy));
    l23 = __floats2bfloat162_rn(v.z - __bfloat162float(hz), v.w - __bfloat162float(hw));
    uint2 uh, ul;
    uh.x = *reinterpret_cast<uint32_t*>(&h01); uh.y = *reinterpret_cast<uint32_t*>(&h23);
    ul.x = *reinterpret_cast<uint32_t*>(&l01); ul.y = *reinterpret_cast<uint32_t*>(&l23);
    ((uint2*)g_x_hi)[i] = uh;
    ((uint2*)g_x_lo)[i] = ul;
}

// ---------------- fold + transpose + bf16-split weights ----------------
__global__ void k_prep(const float* __restrict__ Wx, const float* __restrict__ bx,
                       const float* __restrict__ Wsl, const float* __restrict__ bsl,
                       const float* __restrict__ Wfx) {
    int c = blockIdx.x;        // K index 0..255
    int o = threadIdx.x;       // N index 0..511
    int h = o >> 6, gg = o & 63;
    float s = 0.f;
    #pragma unroll 16
    for (int d = 0; d < 64; d++)
        s += Wx[c*INNER + h*64 + d] * Wsl[d*64 + gg];
    __nv_bfloat16 sh = __float2bfloat16(s);
    g_wslT_hi[o*CC + c] = sh;
    g_wslT_lo[o*CC + c] = __float2bfloat16(s - __bfloat162float(sh));
    float v = Wfx[c*INNER + o];
    __nv_bfloat16 vh = __float2bfloat16(v);
    g_wfxT_hi[o*CC + c] = vh;
    g_wfxT_lo[o*CC + c] = __float2bfloat16(v - __bfloat162float(vh));
    if (c == 0) {
        float t = 0.f;
        #pragma unroll 16
        for (int d = 0; d < 64; d++) t += bx[h*64 + d] * Wsl[d*64 + gg];
        g_bsl[o] = t + bsl[gg];
    }
}

// ---------------- projection GEMM (mma.sync): FX or slice-softmax ----------------
// block M128 x N128, K=256 x 3 segments (12 chunks of 64). grid (8, 1024):
// blockIdx.x = column tile (fast-varying -> A tiles L2-resident), blockIdx.y = tileM.
// 3-stage cp.async pipeline, one barrier per chunk.
__global__ __launch_bounds__(256, 2) void k_proj(const float* __restrict__ bfx,
                                                 const float* __restrict__ temp) {
    extern __shared__ char sm[];
    float* stage = (float*)sm;
    uint32_t sb = smem_u32(sm);
    int tid = threadIdx.x;
    int lane = tid & 31, w = tid >> 5;
    int wm = w & 1, wn = w >> 1;
    int tileM = blockIdx.y, yb = blockIdx.x;
    bool isFX = yb < 4;
    int y2 = isFX ? yb : yb - 4;
    int row0 = tileM * 128;
    const __nv_bfloat16* Bhi = isFX ? g_wfxT_hi : g_wslT_hi;
    const __nv_bfloat16* Blo = isFX ? g_wfxT_lo : g_wslT_lo;

    float acc[4][4][4];
    #pragma unroll
    for (int a = 0; a < 4; a++)
        #pragma unroll
        for (int b = 0; b < 4; b++)
            #pragma unroll
            for (int d = 0; d < 4; d++) acc[a][b][d] = 0.f;

    auto issue = [&](int c) {
        int p = c % 3, seg = c >> 2, k0 = (c & 3) * 64;
        const __nv_bfloat16* As = (seg == 2) ? g_x_lo : g_x_hi;
        const __nv_bfloat16* Bs = (seg == 1) ? Blo : Bhi;
        #pragma unroll
        for (int i = 0; i < 4; i++) {
            int id = tid + i * 256, r = id >> 3, c8 = (id & 7) * 8;
            cpa16(sb + p*32768 + SWZ((uint32_t)(r*128 + c8*2)),
                  As + (size_t)(row0 + r) * CC + k0 + c8);
        }
        #pragma unroll
        for (int i = 0; i < 4; i++) {
            int id = tid + i * 256, r = id >> 3, c8 = (id & 7) * 8;
            cpa16(sb + p*32768 + 16384 + SWZ((uint32_t)(r*128 + c8*2)),
                  Bs + (size_t)(y2*128 + r) * CC + k0 + c8);
        }
        CP_COMMIT();
    };

    issue(0); issue(1);
    for (int c = 0; c < 12; c++) {
        if (c + 1 < 12) CP_WAIT1(); else CP_WAIT0();
        __syncthreads();
        uint32_t ab = sb + (c % 3) * 32768;
        uint32_t bb = ab + 16384;
        int rA = lane & 15;
        #pragma unroll
        for (int kk = 0; kk < 4; kk++) {
            uint32_t af[4][4], bf[2][4];
            int kc = kk * 16 + (lane >> 4) * 8;
            #pragma unroll
            for (int mi = 0; mi < 4; mi++)
                ldsm4(af[mi], ab + SWZ((uint32_t)((wm*64 + mi*16 + rA)*128 + kc*2)));
            #pragma unroll
            for (int s = 0; s < 2; s++)
                ldsm4(bf[s], bb + SWZ((uint32_t)((wn*32 + s*16 + rA)*128 + kc*2)));
            #pragma unroll
            for (int mi = 0; mi < 4; mi++)
                #pragma unroll
                for (int nj = 0; nj < 4; nj++)
                    mma_bf16(acc[mi][nj], af[mi][0], af[mi][1], af[mi][2], af[mi][3],
                             bf[nj>>1][nj&1], bf[nj>>1][(nj&1)+2]);
        }
        if (c + 2 < 12) issue(c + 2);
    }
    __syncthreads();   // all warps done with buffers before stage alias reuse

    // frags -> stage
    #pragma unroll
    for (int mi = 0; mi < 4; mi++)
        #pragma unroll
        for (int nj = 0; nj < 4; nj++) {
            int row = wm*64 + mi*16 + (lane >> 2);
            int col = wn*32 + nj*8 + (lane & 3)*2;
            *(float2*)&stage[row*STG + col]     = make_float2(acc[mi][nj][0], acc[mi][nj][1]);
            *(float2*)&stage[(row+8)*STG + col] = make_float2(acc[mi][nj][2], acc[mi][nj][3]);
        }
    __syncthreads();

    if (isFX) {
        #pragma unroll
        for (int i = 0; i < 16; i++) {
            int lin = tid + i * 256, r = lin >> 5, c4 = (lin & 31) * 4;
            float4 v = *(float4*)&stage[r*STG + c4];
            float4 bv = *(const float4*)&bfx[y2*128 + c4];
            v.x += bv.x; v.y += bv.y; v.z += bv.z; v.w += bv.w;
            *(float4*)&g_fx[(size_t)(row0 + r)*INNER + y2*128 + c4] = v;
        }
    } else {
        float rt0 = 1.0f / fminf(fmaxf(temp[y2*2 + 0], 0.1f), 5.0f);
        float rt1 = 1.0f / fminf(fmaxf(temp[y2*2 + 1], 0.1f), 5.0f);
        // warp w handles groups w*32 .. w*32+31 (group = row*2 + head)
        for (int gi = 0; gi < 32; gi++) {
            int G = w * 32 + gi;
            int r = G >> 1, hh = G & 1;
            float bb0 = g_bsl[y2*128 + hh*64 + lane];
            float bb1 = g_bsl[y2*128 + hh*64 + 32 + lane];
            float rt = hh ? rt1 : rt0;
            float v0 = (stage[r*STG + hh*64 + lane]      + bb0) * rt;
            float v1 = (stage[r*STG + hh*64 + 32 + lane] + bb1) * rt;
            float m = fmaxf(v0, v1);
            #pragma unroll
            for (int o = 16; o; o >>= 1) m = fmaxf(m, __shfl_xor_sync(0xFFFFFFFFu, m, o));
            float e0 = __expf(v0 - m), e1 = __expf(v1 - m);
            float s = e0 + e1;
            #pragma unroll
            for (int o = 16; o; o >>= 1) s += __shfl_xor_sync(0xFFFFFFFFu, s, o);
            float rs = 1.0f / s;
            stage[r*STG + hh*64 + lane]      = e0 * rs;
            stage[r*STG + hh*64 + 32 + lane] = e1 * rs;
        }
        __syncthreads();
        #pragma unroll
        for (int i = 0; i < 16; i++) {
            int lin = tid + i * 256, r = lin >> 5, c4 = (lin & 31) * 4;
            float4 v = *(float4*)&stage[r*STG + c4];
            __nv_bfloat16 hx = __float2bfloat16(v.x), hy = __float2bfloat16(v.y);
            __nv_bfloat16 hz = __float2bfloat16(v.z), hw = __float2bfloat16(v.w);
            __nv_bfloat162 h01(hx, hy), h23(hz, hw);
            __nv_bfloat162 l01 = __floats2bfloat162_rn(v.x - __bfloat162float(hx),
                                                       v.y - __bfloat162float(hy));
            __nv_bfloat162 l23 = __floats2bfloat162_rn(v.z - __bfloat162float(hz),
                                                       v.w - __bfloat162float(hw));
            uint2 uh, ul;
            uh.x = *reinterpret_cast<uint32_t*>(&h01); uh.y = *reinterpret_cast<uint32_t*>(&h23);
            ul.x = *reinterpret_cast<uint32_t*>(&l01); ul.y = *reinterpret_cast<uint32_t*>(&l23);
            size_t idx = (size_t)(row0 + r)*INNER + y2*128 + c4;
            *(uint2*)&g_w_hi[idx] = uh;
            *(uint2*)&g_w_lo[idx] = ul;
        }
    }
}

// ---------------- pooling: ST[bh][g][d] += w*fx ; norm[g] += w ----------------
// 32-token double-buffered stages; fx via cp.async, w prefetched to regs.
// norm: per-thread column-pair partials (cols {2*(tid&31), 2*(tid&31)+1}).
__global__ __launch_bounds__(256) void k_pool() {
    int bh = blockIdx.x, chunk = blockIdx.y;
    int b = bh >> 3, h = bh & 7;
    int tid = threadIdx.x;
    int tx = tid & 15, ty = tid >> 4;
    __shared__ float fs[2][32][68];
    __shared__ float ws[2][32][68];
    float acc[4][4];
    #pragma unroll
    for (int i = 0; i < 4; i++)
        #pragma unroll
        for (int j = 0; j < 4; j++) acc[i][j] = 0.f;
    float pn0 = 0.f, pn1 = 0.f;     // partial norms for the two owned columns

    const int TPC = NTOK / 16;     // 2048 tokens per chunk
    const int NST = TPC / 32;      // 64 stages
    int t0 = b * NTOK + chunk * TPC;
    int fr = tid >> 3, fc = (tid & 7) * 8;
    uint32_t wh[4], wl[4];

    auto loadFX = [&](int s, int p) {
        const float* src = g_fx + (size_t)(t0 + s*32 + fr) * INNER + h*64 + fc;
        cpa16(smem_u32(&fs[p][fr][fc]),     src);
        cpa16(smem_u32(&fs[p][fr][fc + 4]), src + 4);
        CP_COMMIT();
    };
    auto loadW = [&](int s) {
        #pragma unroll
        for (int i = 0; i < 4; i++) {
            int pid = tid + i * 256;
            int wr = pid >> 5, wg = (pid & 31) * 2;
            size_t idx = (size_t)(t0 + s*32 + wr) * INNER + h*64 + wg;
            wh[i] = *(const uint32_t*)&g_w_hi[idx];
            wl[i] = *(const uint32_t*)&g_w_lo[idx];
        }
    };
    auto storeW = [&](int p) {
        #pragma unroll
        for (int i = 0; i < 4; i++) {
            int pid = tid + i * 256;
            int wr = pid >> 5, wg = (pid & 31) * 2;
            float2 hv = __bfloat1622float2(*(__nv_bfloat162*)&wh[i]);
            float2 lv = __bfloat1622float2(*(__nv_bfloat162*)&wl[i]);
            float v0 = hv.x + lv.x, v1 = hv.y + lv.y;
            ws[p][wr][wg] = v0; ws[p][wr][wg + 1] = v1;
            pn0 += v0; pn1 += v1;
        }
    };

    loadW(0);
    loadFX(0, 0);
    storeW(0);
    for (int s = 0; s < NST; s++) {
        int p = s & 1;
        if (s + 1 < NST) { loadW(s + 1); loadFX(s + 1, 1 - p); CP_WAIT1(); }
        else CP_WAIT0();
        __syncthreads();
        #pragma unroll 8
        for (int t = 0; t < 32; t++) {
            float4 a  = *(float4*)&ws[p][t][ty * 4];
            float4 bb = *(float4*)&fs[p][t][tx * 4];
            acc[0][0] += a.x*bb.x; acc[0][1] += a.x*bb.y; acc[0][2] += a.x*bb.z; acc[0][3] += a.x*bb.w;
            acc[1][0] += a.y*bb.x; acc[1][1] += a.y*bb.y; acc[1][2] += a.y*bb.z; acc[1][3] += a.y*bb.w;
            acc[2][0] += a.z*bb.x; acc[2][1] += a.z*bb.y; acc[2][2] += a.z*bb.z; acc[2][3] += a.z*bb.w;
            acc[3][0] += a.w*bb.x; acc[3][1] += a.w*bb.y; acc[3][2] += a.w*bb.z; acc[3][3] += a.w*bb.w;
        }
        __syncthreads();
        if (s + 1 < NST) storeW(1 - p);
    }
    #pragma unroll
    for (int i = 0; i < 4; i++)
        #pragma unroll
        for (int j = 0; j < 4; j++)
            atomicAdd(&g_st[bh * 4096 + (ty*4 + i) * 64 + tx*4 + j], acc[i][j]);

    __shared__ float nr0[256], nr1[256];
    nr0[tid] = pn0; nr1[tid] = pn1;
    __syncthreads();
    if (tid < 32) {     // owner of column pair {2*tid, 2*tid+1}
        float s0 = 0.f, s1 = 0.f;
        #pragma unroll
        for (int j = 0; j < 8; j++) { s0 += nr0[tid + j*32]; s1 += nr1[tid + j*32]; }
        atomicAdd(&g_norm[bh * 64 + 2*tid],     s0);
        atomicAdd(&g_norm[bh * 64 + 2*tid + 1], s1);
    }
}

// ---------------- tiny attention over slice tokens ----------------
__global__ void k_attn(const float* __restrict__ Wq, const float* __restrict__ Wk,
                       const float* __restrict__ Wv) {
    int bh = blockIdx.x;
    int tid = threadIdx.x;
    __shared__ float sn[64][64];
    __shared__ float ks[64][64];
    __shared__ float nrm[64];
    if (tid < 64) nrm[tid] = g_norm[bh * 64 + tid] + 1e-5f;
    __syncthreads();
    #pragma unroll
    for (int it = 0; it < 16; it++) {
        int idx = tid + it * 256;
        int g2 = idx >> 6;
        sn[g2][idx & 63] = g_st[bh * 4096 + idx] / nrm[g2];
    }
    __syncthreads();
    #pragma unroll
    for (int it = 0; it < 16; it++) {
        int idx = tid + it * 256;
        int g2 = idx >> 6, d2 = idx & 63;
        float s0 = 0, s1 = 0, s2 = 0, s3 = 0;
        #pragma unroll
        for (int d = 0; d < 64; d += 4) {
            s0 += sn[g2][d]   * Wk[(d)   * 64 + d2];
            s1 += sn[g2][d+1] * Wk[(d+1) * 64 + d2];
            s2 += sn[g2][d+2] * Wk[(d+2) * 64 + d2];
            s3 += sn[g2][d+3] * Wk[(d+3) * 64 + d2];
        }
        ks[g2][d2] = (s0 + s1) + (s2 + s3);
    }
    __syncthreads();
    float tv[64];
    if (tid < 64) {
        int g2 = tid;
        float q[64];
        #pragma unroll
        for (int d2 = 0; d2 < 64; d2++) {
            float s0 = 0, s1 = 0, s2 = 0, s3 = 0;
            #pragma unroll
            for (int d = 0; d < 64; d += 4) {
                s0 += sn[g2][d]   * Wq[(d)   * 64 + d2];
                s1 += sn[g2][d+1] * Wq[(d+1) * 64 + d2];
                s2 += sn[g2][d+2] * Wq[(d+2) * 64 + d2];
                s3 += sn[g2][d+3] * Wq[(d+3) * 64 + d2];
            }
            q[d2] = (s0 + s1) + (s2 + s3);
        }
        float p[64];
        float mx = -1e30f;
        #pragma unroll
        for (int j = 0; j < 64; j++) {
            float s0 = 0, s1 = 0, s2 = 0, s3 = 0;
            #pragma unroll
            for (int d = 0; d < 64; d += 4) {
                s0 += q[d]   * ks[j][d];
                s1 += q[d+1] * ks[j][d+1];
                s2 += q[d+2] * ks[j][d+2];
                s3 += q[d+3] * ks[j][d+3];
            }
            float s = ((s0 + s1) + (s2 + s3)) * 0.125f;
            p[j] = s;
            mx = fmaxf(mx, s);
        }
        float sum = 0.f;
        #pragma unroll
        for (int j = 0; j < 64; j++) { p[j] = __expf(p[j] - mx); sum += p[j]; }
        float rs = 1.0f / sum;
        #pragma unroll
        for (int e = 0; e < 64; e++) {
            float s0 = 0, s1 = 0, s2 = 0, s3 = 0;
            #pragma unroll
            for (int j = 0; j < 64; j += 4) {
                s0 += p[j]   * sn[j][e];
                s1 += p[j+1] * sn[j+1][e];
                s2 += p[j+2] * sn[j+2][e];
                s3 += p[j+3] * sn[j+3][e];
            }
            tv[e] = ((s0 + s1) + (s2 + s3)) * rs;
        }
    }
    __syncthreads();
    if (tid < 64) {
        #pragma unroll
        for (int e = 0; e < 64; e++) ks[tid][e] = tv[e];
    }
    __syncthreads();
    #pragma unroll
    for (int it = 0; it < 16; it++) {
        int idx = tid + it * 256;
        int g2 = idx >> 6, d2 = idx & 63;
        float s0 = 0, s1 = 0, s2 = 0, s3 = 0;
        #pragma unroll
        for (int e = 0; e < 64; e += 4) {
            s0 += ks[g2][e]   * Wv[(e)   * 64 + d2];
            s1 += ks[g2][e+1] * Wv[(e+1) * 64 + d2];
            s2 += ks[g2][e+2] * Wv[(e+2) * 64 + d2];
            s3 += ks[g2][e+3] * Wv[(e+3) * 64 + d2];
        }
        g_os[bh * 4096 + idx] = (s0 + s1) + (s2 + s3);
    }
}

// ---------------- fold out_slice into W_out: W_eff^T pair [b][n=256][k=512] ----------------
__global__ void k_weff(const float* __restrict__ Wout) {
    int blk = blockIdx.x;           // b*512 + row
    int b = blk >> 9;
    int row = blk & 511;            // k index: h*64+g
    int h = row >> 6;
    int tid = threadIdx.x;          // n index = c (256)
    __shared__ float osr[64];
    if (tid < 64) osr[tid] = g_os[(b*8 + h) * 4096 + (row & 63) * 64 + tid];
    __syncthreads();
    float s = 0.f;
    #pragma unroll 16
    for (int d = 0; d < 64; d++)
        s += osr[d] * Wout[(h*64 + d) * CC + tid];
    __nv_bfloat16 sh = __float2bfloat16(s);
    size_t idx = (size_t)b * (CC*INNER) + (size_t)tid * INNER + row;
    g_weffT_hi[idx] = sh;
    g_weffT_lo[idx] = __float2bfloat16(s - __bfloat162float(sh));
}

// ---------------- output GEMM (mma.sync): y = w @ W_eff[b] + b_out ----------------
// block M128 x N128, K=512 x 3 segments (24 chunks). grid (2, 1024): ct fast-varying.
// 3-stage cp.async pipeline, one barrier per chunk.
__global__ __launch_bounds__(256, 2) void k_out(const float* __restrict__ bout,
                                                float* __restrict__ y) {
    extern __shared__ char sm[];
    float* stage = (float*)sm;
    uint32_t sb = smem_u32(sm);
    int tid = threadIdx.x;
    int lane = tid & 31, w = tid >> 5;
    int wm = w & 1, wn = w >> 1;
    int tileM = blockIdx.y, ct = blockIdx.x;
    int row0 = tileM * 128;
    int b = tileM >> 8;

    float acc[4][4][4];
    #pragma unroll
    for (int a = 0; a < 4; a++)
        #pragma unroll
        for (int bb2 = 0; bb2 < 4; bb2++)
            #pragma unroll
            for (int d = 0; d < 4; d++) acc[a][bb2][d] = 0.f;

    auto issue = [&](int c) {
        int p = c % 3, seg = c >> 3, k0 = (c & 7) * 64;
        const __nv_bfloat16* As = (seg == 2) ? g_w_lo : g_w_hi;
        const __nv_bfloat16* Bs = (seg == 1) ? g_weffT_lo : g_weffT_hi;
        #pragma unroll
        for (int i = 0; i < 4; i++) {
            int id = tid + i * 256, r = id >> 3, c8 = (id & 7) * 8;
            cpa16(sb + p*32768 + SWZ((uint32_t)(r*128 + c8*2)),
                  As + (size_t)(row0 + r) * INNER + k0 + c8);
        }
        #pragma unroll
        for (int i = 0; i < 4; i++) {
            int id = tid + i * 256, r = id >> 3, c8 = (id & 7) * 8;
            cpa16(sb + p*32768 + 16384 + SWZ((uint32_t)(r*128 + c8*2)),
                  Bs + (size_t)b * (CC*INNER) + (size_t)(ct*128 + r) * INNER + k0 + c8);
        }
        CP_COMMIT();
    };

    issue(0); issue(1);
    for (int c = 0; c < 24; c++) {
        if (c + 1 < 24) CP_WAIT1(); else CP_WAIT0();
        __syncthreads();
        uint32_t ab = sb + (c % 3) * 32768;
        uint32_t bbs = ab + 16384;
        int rA = lane & 15;
        #pragma unroll
        for (int kk = 0; kk < 4; kk++) {
            uint32_t af[4][4], bf[2][4];
            int kc = kk * 16 + (lane >> 4) * 8;
            #pragma unroll
            for (int mi = 0; mi < 4; mi++)
                ldsm4(af[mi], ab + SWZ((uint32_t)((wm*64 + mi*16 + rA)*128 + kc*2)));
            #pragma unroll
            for (int s = 0; s < 2; s++)
                ldsm4(bf[s], bbs + SWZ((uint32_t)((wn*32 + s*16 + rA)*128 + kc*2)));
            #pragma unroll
            for (int mi = 0; mi < 4; mi++)
                #pragma unroll
                for (int nj = 0; nj < 4; nj++)
                    mma_bf16(acc[mi][nj], af[mi][0], af[mi][1], af[mi][2], af[mi][3],
                             bf[nj>>1][nj&1], bf[nj>>1][(nj&1)+2]);
        }
        if (c + 2 < 24) issue(c + 2);
    }
    __syncthreads();   // buffers done before stage alias reuse

    #pragma unroll
    for (int mi = 0; mi < 4; mi++)
        #pragma unroll
        for (int nj = 0; nj < 4; nj++) {
            int row = wm*64 + mi*16 + (lane >> 2);
            int col = wn*32 + nj*8 + (lane & 3)*2;
            *(float2*)&stage[row*STG + col]     = make_float2(acc[mi][nj][0], acc[mi][nj][1]);
            *(float2*)&stage[(row+8)*STG + col] = make_float2(acc[mi][nj][2], acc[mi][nj][3]);
        }
    __syncthreads();
    #pragma unroll
    for (int i = 0; i < 16; i++) {
        int lin = tid + i * 256, r = lin >> 5, c4 = (lin & 31) * 4;
        float4 v = *(float4*)&stage[r*STG + c4];
        float4 bv = *(const float4*)&bout[ct*128 + c4];
        v.x += bv.x; v.y += bv.y; v.z += bv.z; v.w += bv.w;
        *(float4*)&y[(size_t)(row0 + r)*CC + ct*128 + c4] = v;
    }
}

// ---------------- launch ----------------
extern "C" void kernel_launch(void* const* d_in, const int* in_sizes, int n_in,
                              void* d_out, int out_size) {
    const float* x    = (const float*)d_in[0];
    const float* Wfx  = (const float*)d_in[1];
    const float* bfx  = (const float*)d_in[2];
    const float* Wx   = (const float*)d_in[3];
    const float* bx   = (const float*)d_in[4];
    const float* Wsl  = (const float*)d_in[5];
    const float* bsl  = (const float*)d_in[6];
    const float* temp = (const float*)d_in[7];
    const float* Wq   = (const float*)d_in[8];
    const float* Wk   = (const float*)d_in[9];
    const float* Wv   = (const float*)d_in[10];
    const float* Wout = (const float*)d_in[11];
    const float* bout = (const float*)d_in[12];
    float* y = (float*)d_out;

    cudaFuncSetAttribute(k_proj, cudaFuncAttributeMaxDynamicSharedMemorySize, GSMEM);
    cudaFuncSetAttribute(k_out,  cudaFuncAttributeMaxDynamicSharedMemorySize, GSMEM);

    k_zero<<<512, 256>>>();
    k_prep<<<CC, 512>>>(Wx, bx, Wsl, bsl, Wfx);
    k_split<<<(TOK*CC/4)/256, 256>>>(x);
    k_proj<<<dim3(8, TOK/128), 256, GSMEM>>>(bfx, temp);
    k_pool<<<dim3(32, 16), 256>>>();
    k_attn<<<32, 256>>>(Wq, Wk, Wv);
    k_weff<<<2048, 256>>>(Wout);
    k_out<<<dim3(2, TOK/128), 256, GSMEM>>>(bout, y);
}

// round 6
// speedup vs baseline: 2.2234x; 1.0527x over previous
#include <cuda_runtime.h>
#include <cuda_bf16.h>
#include <cstdint>

#define BB 4
#define NTOK 32768
#define CC 256
#define HH 8
#define DD 64
#define GG 64
#define INNER 512
#define TOK (BB*NTOK)   // 131072

// ---------------- scratch (device globals; no runtime allocation) ----------------
__device__ __align__(16) __nv_bfloat16 g_x_hi[(size_t)TOK*CC];   // x split bf16 [tok][c]
__device__ __align__(16) __nv_bfloat16 g_x_lo[(size_t)TOK*CC];
__device__ __align__(16) __nv_bfloat16 g_xT_hi[(size_t)BB*CC*NTOK]; // x^T [b][c][n]
__device__ __align__(16) __nv_bfloat16 g_xT_lo[(size_t)BB*CC*NTOK];
__device__ __align__(16) __nv_bfloat16 g_w_hi[(size_t)TOK*INNER];// slice weights [tok][hg]
__device__ __align__(16) __nv_bfloat16 g_w_lo[(size_t)TOK*INNER];
__device__ __align__(16) __nv_bfloat16 g_wT_hi[(size_t)BB*HH*GG*NTOK]; // w^T [bh][g][n]
__device__ __align__(16) __nv_bfloat16 g_wT_lo[(size_t)BB*HH*GG*NTOK];
__device__ __align__(16) __nv_bfloat16 g_wslT_hi[INNER*CC];      // (Wx@Wslice)^T split
__device__ __align__(16) __nv_bfloat16 g_wslT_lo[INNER*CC];
__device__ float g_bsl[INNER];                    // folded slice bias
__device__ float g_P[BB*HH*GG*CC];                // pooled P[bh][g][c] (atomic accum)
__device__ float g_st[BB*HH*GG*DD];               // slice token sums
__device__ float g_norm[BB*HH*GG];                // weight column sums
__device__ float g_os[BB*HH*GG*DD];               // out_slice
__device__ __align__(16) __nv_bfloat16 g_weffT_hi[BB*CC*INNER];  // W_eff^T [b][n=256][k=512]
__device__ __align__(16) __nv_bfloat16 g_weffT_lo[BB*CC*INNER];

// ============================ helpers ============================
#define DINLINE __device__ __forceinline__

DINLINE uint32_t smem_u32(const void* p) {
    uint32_t a;
    asm("{ .reg .u64 t; cvta.to.shared.u64 t, %1; cvt.u32.u64 %0, t; }" : "=r"(a) : "l"(p));
    return a;
}
DINLINE void cpa16(uint32_t dst, const void* src) {
    asm volatile("cp.async.ca.shared.global [%0], [%1], 16;" :: "r"(dst), "l"(src));
}
#define CP_COMMIT() asm volatile("cp.async.commit_group;" ::: "memory")
#define CP_WAIT1()  asm volatile("cp.async.wait_group 1;" ::: "memory")
#define CP_WAIT0()  asm volatile("cp.async.wait_group 0;" ::: "memory")

DINLINE void ldsm4(uint32_t* r, uint32_t addr) {
    asm volatile("ldmatrix.sync.aligned.m8n8.x4.shared.b16 {%0,%1,%2,%3}, [%4];"
        : "=r"(r[0]), "=r"(r[1]), "=r"(r[2]), "=r"(r[3]) : "r"(addr));
}
DINLINE void mma_bf16(float* d, uint32_t a0, uint32_t a1, uint32_t a2, uint32_t a3,
                      uint32_t b0, uint32_t b1) {
    asm volatile("mma.sync.aligned.m16n8k16.row.col.f32.bf16.bf16.f32 "
        "{%0,%1,%2,%3}, {%4,%5,%6,%7}, {%8,%9}, {%0,%1,%2,%3};"
        : "+f"(d[0]), "+f"(d[1]), "+f"(d[2]), "+f"(d[3])
        : "r"(a0), "r"(a1), "r"(a2), "r"(a3), "r"(b0), "r"(b1));
}
#define SWZ(off) ((off) ^ (((off) >> 3) & 0x70))
#define STG 132        // stage row stride (floats)
#define GSMEM 98304    // 3 stages x (16KB A + 16KB B) for proj/out
#define PGSMEM 73728   // 3 stages x (8KB A + 16KB B) for poolg

// ---------------- zero accumulators (must run every graph replay) ----------------
__global__ void k_zero() {
    int i = blockIdx.x * blockDim.x + threadIdx.x;
    if (i < BB*HH*GG*CC) g_P[i] = 0.f;
    if (i < BB*HH*GG)    g_norm[i] = 0.f;
}

// ---------------- split x into bf16 hi/lo, both [tok][c] and transposed ----------------
__global__ void k_split(const float* __restrict__ x) {
    __shared__ uint16_t shi[64][68], slo[64][68];
    int tid = threadIdx.x;
    size_t t0 = (size_t)blockIdx.x * 64;     // token tile
    int c0 = blockIdx.y * 64;                // c tile
    int r = tid >> 2, cq = (tid & 3) * 16;
    #pragma unroll
    for (int j = 0; j < 16; j += 4) {
        float4 v = *(const float4*)&x[(t0 + r) * CC + c0 + cq + j];
        __nv_bfloat16 hx = __float2bfloat16(v.x), hy = __float2bfloat16(v.y);
        __nv_bfloat16 hz = __float2bfloat16(v.z), hw = __float2bfloat16(v.w);
        __nv_bfloat162 h01(hx, hy), h23(hz, hw);
        __nv_bfloat162 l01 = __floats2bfloat162_rn(v.x - __bfloat162float(hx),
                                                   v.y - __bfloat162float(hy));
        __nv_bfloat162 l23 = __floats2bfloat162_rn(v.z - __bfloat162float(hz),
                                                   v.w - __bfloat162float(hw));
        uint2 uh, ul;
        uh.x = *reinterpret_cast<uint32_t*>(&h01); uh.y = *reinterpret_cast<uint32_t*>(&h23);
        ul.x = *reinterpret_cast<uint32_t*>(&l01); ul.y = *reinterpret_cast<uint32_t*>(&l23);
        *(uint2*)&g_x_hi[(t0 + r) * CC + c0 + cq + j] = uh;
        *(uint2*)&g_x_lo[(t0 + r) * CC + c0 + cq + j] = ul;
        *(uint2*)&shi[r][cq + j] = uh;
        *(uint2*)&slo[r][cq + j] = ul;
    }
    __syncthreads();
    int c = tid >> 2, tq = (tid & 3) * 16;
    size_t b = t0 >> 15;                 // /NTOK
    size_t nloc = t0 & (NTOK - 1);
    size_t base = ((size_t)b * CC + c0 + c) * NTOK + nloc + tq;
    #pragma unroll
    for (int j = 0; j < 16; j += 2) {
        uint32_t hv = (uint32_t)shi[tq + j][c] | ((uint32_t)shi[tq + j + 1][c] << 16);
        uint32_t lv = (uint32_t)slo[tq + j][c] | ((uint32_t)slo[tq + j + 1][c] << 16);
        *(uint32_t*)&g_xT_hi[base + j] = hv;
        *(uint32_t*)&g_xT_lo[base + j] = lv;
    }
}

// ---------------- fold + transpose + bf16-split slice weight ----------------
__global__ void k_prep(const float* __restrict__ Wx, const float* __restrict__ bx,
                       const float* __restrict__ Wsl, const float* __restrict__ bsl) {
    int c = blockIdx.x;        // K index 0..255
    int o = threadIdx.x;       // N index 0..511
    int h = o >> 6, gg = o & 63;
    float s = 0.f;
    #pragma unroll 16
    for (int d = 0; d < 64; d++)
        s += Wx[c*INNER + h*64 + d] * Wsl[d*64 + gg];
    __nv_bfloat16 sh = __float2bfloat16(s);
    g_wslT_hi[o*CC + c] = sh;
    g_wslT_lo[o*CC + c] = __float2bfloat16(s - __bfloat162float(sh));
    if (c == 0) {
        float t = 0.f;
        #pragma unroll 16
        for (int d = 0; d < 64; d++) t += bx[h*64 + d] * Wsl[d*64 + gg];
        g_bsl[o] = t + bsl[gg];
    }
}

// ---------------- slice-logits GEMM + softmax (mma.sync) ----------------
// block M128 x N128, K=256 x 3 segments (12 chunks of 64). grid (4, 1024).
// Epilogue: softmax -> w pair [tok][hg], w^T pair [bh][g][n], norm atomics.
__global__ __launch_bounds__(256, 2) void k_proj(const float* __restrict__ temp) {
    extern __shared__ char sm[];
    float* stage = (float*)sm;
    uint32_t sb = smem_u32(sm);
    int tid = threadIdx.x;
    int lane = tid & 31, w = tid >> 5;
    int wm = w & 1, wn = w >> 1;
    int tileM = blockIdx.y, y2 = blockIdx.x;
    int row0 = tileM * 128;
    int b = tileM >> 8;                       // 256 tiles per batch
    size_t row0loc = (size_t)(tileM & 255) * 128;

    float acc[4][4][4];
    #pragma unroll
    for (int a = 0; a < 4; a++)
        #pragma unroll
        for (int b2 = 0; b2 < 4; b2++)
            #pragma unroll
            for (int d = 0; d < 4; d++) acc[a][b2][d] = 0.f;

    auto issue = [&](int c) {
        int p = c % 3, seg = c >> 2, k0 = (c & 3) * 64;
        const __nv_bfloat16* As = (seg == 2) ? g_x_lo : g_x_hi;
        const __nv_bfloat16* Bs = (seg == 1) ? g_wslT_lo : g_wslT_hi;
        #pragma unroll
        for (int i = 0; i < 4; i++) {
            int id = tid + i * 256, r = id >> 3, c8 = (id & 7) * 8;
            cpa16(sb + p*32768 + SWZ((uint32_t)(r*128 + c8*2)),
                  As + (size_t)(row0 + r) * CC + k0 + c8);
        }
        #pragma unroll
        for (int i = 0; i < 4; i++) {
            int id = tid + i * 256, r = id >> 3, c8 = (id & 7) * 8;
            cpa16(sb + p*32768 + 16384 + SWZ((uint32_t)(r*128 + c8*2)),
                  Bs + (size_t)(y2*128 + r) * CC + k0 + c8);
        }
        CP_COMMIT();
    };

    issue(0); issue(1);
    for (int c = 0; c < 12; c++) {
        if (c + 1 < 12) CP_WAIT1(); else CP_WAIT0();
        __syncthreads();
        uint32_t ab = sb + (c % 3) * 32768;
        uint32_t bb = ab + 16384;
        int rA = lane & 15;
        #pragma unroll
        for (int kk = 0; kk < 4; kk++) {
            uint32_t af[4][4], bf[2][4];
            int kc = kk * 16 + (lane >> 4) * 8;
            #pragma unroll
            for (int mi = 0; mi < 4; mi++)
                ldsm4(af[mi], ab + SWZ((uint32_t)((wm*64 + mi*16 + rA)*128 + kc*2)));
            #pragma unroll
            for (int s = 0; s < 2; s++)
                ldsm4(bf[s], bb + SWZ((uint32_t)((wn*32 + s*16 + rA)*128 + kc*2)));
            #pragma unroll
            for (int mi = 0; mi < 4; mi++)
                #pragma unroll
                for (int nj = 0; nj < 4; nj++)
                    mma_bf16(acc[mi][nj], af[mi][0], af[mi][1], af[mi][2], af[mi][3],
                             bf[nj>>1][nj&1], bf[nj>>1][(nj&1)+2]);
        }
        if (c + 2 < 12) issue(c + 2);
    }
    __syncthreads();

    // frags -> stage
    #pragma unroll
    for (int mi = 0; mi < 4; mi++)
        #pragma unroll
        for (int nj = 0; nj < 4; nj++) {
            int row = wm*64 + mi*16 + (lane >> 2);
            int col = wn*32 + nj*8 + (lane & 3)*2;
            *(float2*)&stage[row*STG + col]     = make_float2(acc[mi][nj][0], acc[mi][nj][1]);
            *(float2*)&stage[(row+8)*STG + col] = make_float2(acc[mi][nj][2], acc[mi][nj][3]);
        }
    __syncthreads();

    // softmax over each head's 64 cols per row
    float rt0 = 1.0f / fminf(fmaxf(temp[y2*2 + 0], 0.1f), 5.0f);
    float rt1 = 1.0f / fminf(fmaxf(temp[y2*2 + 1], 0.1f), 5.0f);
    for (int gi = 0; gi < 32; gi++) {
        int G = w * 32 + gi;
        int r = G >> 1, hh = G & 1;
        float bb0 = g_bsl[y2*128 + hh*64 + lane];
        float bb1 = g_bsl[y2*128 + hh*64 + 32 + lane];
        float rt = hh ? rt1 : rt0;
        float v0 = (stage[r*STG + hh*64 + lane]      + bb0) * rt;
        float v1 = (stage[r*STG + hh*64 + 32 + lane] + bb1) * rt;
        float m = fmaxf(v0, v1);
        #pragma unroll
        for (int o = 16; o; o >>= 1) m = fmaxf(m, __shfl_xor_sync(0xFFFFFFFFu, m, o));
        float e0 = __expf(v0 - m), e1 = __expf(v1 - m);
        float s = e0 + e1;
        #pragma unroll
        for (int o = 16; o; o >>= 1) s += __shfl_xor_sync(0xFFFFFFFFu, s, o);
        float rs = 1.0f / s;
        stage[r*STG + hh*64 + lane]      = e0 * rs;
        stage[r*STG + hh*64 + 32 + lane] = e1 * rs;
    }
    __syncthreads();

    // (a) norm: column sums -> atomic
    if (tid < 128) {
        float s = 0.f;
        #pragma unroll 8
        for (int r = 0; r < 128; r++) s += stage[r*STG + tid];
        int head = tid >> 6, g = tid & 63;
        atomicAdd(&g_norm[(b*8 + y2*2 + head)*64 + g], s);
    }
    // (b) w pair [tok][hg]
    #pragma unroll
    for (int i = 0; i < 16; i++) {
        int lin = tid + i * 256, r = lin >> 5, c4 = (lin & 31) * 4;
        float4 v = *(float4*)&stage[r*STG + c4];
        __nv_bfloat16 hx = __float2bfloat16(v.x), hy = __float2bfloat16(v.y);
        __nv_bfloat16 hz = __float2bfloat16(v.z), hw = __float2bfloat16(v.w);
        __nv_bfloat162 h01(hx, hy), h23(hz, hw);
        __nv_bfloat162 l01 = __floats2bfloat162_rn(v.x - __bfloat162float(hx),
                                                   v.y - __bfloat162float(hy));
        __nv_bfloat162 l23 = __floats2bfloat162_rn(v.z - __bfloat162float(hz),
                                                   v.w - __bfloat162float(hw));
        uint2 uh, ul;
        uh.x = *reinterpret_cast<uint32_t*>(&h01); uh.y = *reinterpret_cast<uint32_t*>(&h23);
        ul.x = *reinterpret_cast<uint32_t*>(&l01); ul.y = *reinterpret_cast<uint32_t*>(&l23);
        size_t idx = (size_t)(row0 + r)*INNER + y2*128 + c4;
        *(uint2*)&g_w_hi[idx] = uh;
        *(uint2*)&g_w_lo[idx] = ul;
    }
    // (c) w^T pair [bh][g][n]
    {
        int cc = tid >> 1, half = tid & 1;
        int head = cc >> 6, g = cc & 63;
        size_t base = ((size_t)(b*8 + y2*2 + head) * 64 + g) * (size_t)NTOK + row0loc;
        #pragma unroll
        for (int i = 0; i < 32; i++) {
            int r = half*64 + 2*i;
            float v0 = stage[r*STG + cc], v1 = stage[(r+1)*STG + cc];
            __nv_bfloat16 h0 = __float2bfloat16(v0), h1 = __float2bfloat16(v1);
            uint32_t hw2 = (uint32_t)*(uint16_t*)&h0 | ((uint32_t)*(uint16_t*)&h1 << 16);
            __nv_bfloat16 l0 = __float2bfloat16(v0 - __bfloat162float(h0));
            __nv_bfloat16 l1 = __float2bfloat16(v1 - __bfloat162float(h1));
            uint32_t lw2 = (uint32_t)*(uint16_t*)&l0 | ((uint32_t)*(uint16_t*)&l1 << 16);
            *(uint32_t*)&g_wT_hi[base + r] = hw2;
            *(uint32_t*)&g_wT_lo[base + r] = lw2;
        }
    }
}

// ---------------- pooling GEMM: P[bh][g][c] = sum_n w[n,g]*x[n,c] ----------------
// block M64(g) x N128(c), K split: grid (32 bh, 16 kc, 2 cb). 96 chunks of 64 k.
__global__ __launch_bounds__(256, 2) void k_poolg() {
    extern __shared__ char sm[];
    uint32_t sb = smem_u32(sm);
    int tid = threadIdx.x;
    int lane = tid & 31, w = tid >> 5;
    int wm = w & 1, wn = w >> 1;          // wm: m32, wn: 0..3 (n32 each)
    int bh = blockIdx.x, kc = blockIdx.y, cb = blockIdx.z;
    int b = bh >> 3;
    size_t nbase = (size_t)kc * 2048;
    const __nv_bfloat16* Ahi = g_wT_hi + (size_t)bh * 64 * NTOK;
    const __nv_bfloat16* Alo = g_wT_lo + (size_t)bh * 64 * NTOK;
    const __nv_bfloat16* Bhi = g_xT_hi + ((size_t)b * CC + cb * 128) * NTOK;
    const __nv_bfloat16* Blo = g_xT_lo + ((size_t)b * CC + cb * 128) * NTOK;

    float acc[2][4][4];
    #pragma unroll
    for (int a = 0; a < 2; a++)
        #pragma unroll
        for (int b2 = 0; b2 < 4; b2++)
            #pragma unroll
            for (int d = 0; d < 4; d++) acc[a][b2][d] = 0.f;

    auto issue = [&](int c) {
        int p = c % 3, seg = c >> 5, k0 = (c & 31) * 64;
        const __nv_bfloat16* As = (seg == 2) ? Alo : Ahi;
        const __nv_bfloat16* Bs = (seg == 1) ? Blo : Bhi;
        #pragma unroll
        for (int i = 0; i < 2; i++) {
            int id = tid + i * 256, r = id >> 3, c8 = (id & 7) * 8;
            cpa16(sb + p*24576 + SWZ((uint32_t)(r*128 + c8*2)),
                  As + (size_t)r * NTOK + nbase + k0 + c8);
        }
        #pragma unroll
        for (int i = 0; i < 4; i++) {
            int id = tid + i * 256, r = id >> 3, c8 = (id & 7) * 8;
            cpa16(sb + p*24576 + 8192 + SWZ((uint32_t)(r*128 + c8*2)),
                  Bs + (size_t)r * NTOK + nbase + k0 + c8);
        }
        CP_COMMIT();
    };

    issue(0); issue(1);
    for (int c = 0; c < 96; c++) {
        if (c + 1 < 96) CP_WAIT1(); else CP_WAIT0();
        __syncthreads();
        uint32_t ab = sb + (c % 3) * 24576;
        uint32_t bb = ab + 8192;
        int rA = lane & 15;
        #pragma unroll
        for (int kk = 0; kk < 4; kk++) {
            uint32_t af[2][4], bf[2][4];
            int kc2 = kk * 16 + (lane >> 4) * 8;
            #pragma unroll
            for (int mi = 0; mi < 2; mi++)
                ldsm4(af[mi], ab + SWZ((uint32_t)((wm*32 + mi*16 + rA)*128 + kc2*2)));
            #pragma unroll
            for (int s = 0; s < 2; s++)
                ldsm4(bf[s], bb + SWZ((uint32_t)((wn*32 + s*16 + rA)*128 + kc2*2)));
            #pragma unroll
            for (int mi = 0; mi < 2; mi++)
                #pragma unroll
                for (int nj = 0; nj < 4; nj++)
                    mma_bf16(acc[mi][nj], af[mi][0], af[mi][1], af[mi][2], af[mi][3],
                             bf[nj>>1][nj&1], bf[nj>>1][(nj&1)+2]);
        }
        if (c + 2 < 96) issue(c + 2);
    }

    #pragma unroll
    for (int mi = 0; mi < 2; mi++)
        #pragma unroll
        for (int nj = 0; nj < 4; nj++) {
            int row = wm*32 + mi*16 + (lane >> 2);
            int col = cb*128 + wn*32 + nj*8 + (lane & 3)*2;
            int base = bh*16384 + row*256 + col;
            atomicAdd(&g_P[base],            acc[mi][nj][0]);
            atomicAdd(&g_P[base + 1],        acc[mi][nj][1]);
            atomicAdd(&g_P[base + 8*256],    acc[mi][nj][2]);
            atomicAdd(&g_P[base + 8*256 + 1],acc[mi][nj][3]);
        }
}

// ---------------- fold: ST[bh][g][d] = P@Wfx + bfx*norm ----------------
__global__ void k_stok(const float* __restrict__ Wfx, const float* __restrict__ bfx) {
    int bh = blockIdx.x;
    int h = bh & 7;
    int tid = threadIdx.x;
    __shared__ float wf[64][65], pp[64][65];
    float acc[16];
    #pragma unroll
    for (int j = 0; j < 16; j++) acc[j] = 0.f;
    int g = tid >> 2, dq = tid & 3;
    for (int c0 = 0; c0 < 4; c0++) {
        #pragma unroll
        for (int i = 0; i < 16; i++) {
            int id = tid + i * 256;
            int r = id >> 6, cl = id & 63;
            wf[r][cl] = Wfx[(c0*64 + r) * INNER + h*64 + cl];
            pp[r][cl] = g_P[bh*16384 + r*256 + c0*64 + cl];
        }
        __syncthreads();
        for (int cl = 0; cl < 64; cl++) {
            float pv = pp[g][cl];
            #pragma unroll
            for (int j = 0; j < 16; j++)
                acc[j] += pv * wf[cl][dq*16 + j];
        }
        __syncthreads();
    }
    float nrm = g_norm[bh*64 + g];
    #pragma unroll
    for (int j = 0; j < 16; j++) {
        int d = dq*16 + j;
        g_st[bh*4096 + g*64 + d] = acc[j] + bfx[h*64 + d] * nrm;
    }
}

// ---------------- tiny attention over slice tokens ----------------
__global__ void k_attn(const float* __restrict__ Wq, const float* __restrict__ Wk,
                       const float* __restrict__ Wv) {
    int bh = blockIdx.x;
    int tid = threadIdx.x;
    __shared__ float sn[64][64];
    __shared__ float ks[64][64];
    __shared__ float nrm[64];
    if (tid < 64) nrm[tid] = g_norm[bh * 64 + tid] + 1e-5f;
    __syncthreads();
    #pragma unroll
    for (int it = 0; it < 16; it++) {
        int idx = tid + it * 256;
        int g2 = idx >> 6;
        sn[g2][idx & 63] = g_st[bh * 4096 + idx] / nrm[g2];
    }
    __syncthreads();
    #pragma unroll
    for (int it = 0; it < 16; it++) {
        int idx = tid + it * 256;
        int g2 = idx >> 6, d2 = idx & 63;
        float s0 = 0, s1 = 0, s2 = 0, s3 = 0;
        #pragma unroll
        for (int d = 0; d < 64; d += 4) {
            s0 += sn[g2][d]   * Wk[(d)   * 64 + d2];
            s1 += sn[g2][d+1] * Wk[(d+1) * 64 + d2];
            s2 += sn[g2][d+2] * Wk[(d+2) * 64 + d2];
            s3 += sn[g2][d+3] * Wk[(d+3) * 64 + d2];
        }
        ks[g2][d2] = (s0 + s1) + (s2 + s3);
    }
    __syncthreads();
    float tv[64];
    if (tid < 64) {
        int g2 = tid;
        float q[64];
        #pragma unroll
        for (int d2 = 0; d2 < 64; d2++) {
            float s0 = 0, s1 = 0, s2 = 0, s3 = 0;
            #pragma unroll
            for (int d = 0; d < 64; d += 4) {
                s0 += sn[g2][d]   * Wq[(d)   * 64 + d2];
                s1 += sn[g2][d+1] * Wq[(d+1) * 64 + d2];
                s2 += sn[g2][d+2] * Wq[(d+2) * 64 + d2];
                s3 += sn[g2][d+3] * Wq[(d+3) * 64 + d2];
            }
            q[d2] = (s0 + s1) + (s2 + s3);
        }
        float p[64];
        float mx = -1e30f;
        #pragma unroll
        for (int j = 0; j < 64; j++) {
            float s0 = 0, s1 = 0, s2 = 0, s3 = 0;
            #pragma unroll
            for (int d = 0; d < 64; d += 4) {
                s0 += q[d]   * ks[j][d];
                s1 += q[d+1] * ks[j][d+1];
                s2 += q[d+2] * ks[j][d+2];
                s3 += q[d+3] * ks[j][d+3];
            }
            float s = ((s0 + s1) + (s2 + s3)) * 0.125f;
            p[j] = s;
            mx = fmaxf(mx, s);
        }
        float sum = 0.f;
        #pragma unroll
        for (int j = 0; j < 64; j++) { p[j] = __expf(p[j] - mx); sum += p[j]; }
        float rs = 1.0f / sum;
        #pragma unroll
        for (int e = 0; e < 64; e++) {
            float s0 = 0, s1 = 0, s2 = 0, s3 = 0;
            #pragma unroll
            for (int j = 0; j < 64; j += 4) {
                s0 += p[j]   * sn[j][e];
                s1 += p[j+1] * sn[j+1][e];
                s2 += p[j+2] * sn[j+2][e];
                s3 += p[j+3] * sn[j+3][e];
            }
            tv[e] = ((s0 + s1) + (s2 + s3)) * rs;
        }
    }
    __syncthreads();
    if (tid < 64) {
        #pragma unroll
        for (int e = 0; e < 64; e++) ks[tid][e] = tv[e];
    }
    __syncthreads();
    #pragma unroll
    for (int it = 0; it < 16; it++) {
        int idx = tid + it * 256;
        int g2 = idx >> 6, d2 = idx & 63;
        float s0 = 0, s1 = 0, s2 = 0, s3 = 0;
        #pragma unroll
        for (int e = 0; e < 64; e += 4) {
            s0 += ks[g2][e]   * Wv[(e)   * 64 + d2];
            s1 += ks[g2][e+1] * Wv[(e+1) * 64 + d2];
            s2 += ks[g2][e+2] * Wv[(e+2) * 64 + d2];
            s3 += ks[g2][e+3] * Wv[(e+3) * 64 + d2];
        }
        g_os[bh * 4096 + idx] = (s0 + s1) + (s2 + s3);
    }
}

// ---------------- fold out_slice into W_out: W_eff^T pair [b][n=256][k=512] ----------------
__global__ void k_weff(const float* __restrict__ Wout) {
    int blk = blockIdx.x;           // b*512 + row
    int b = blk >> 9;
    int row = blk & 511;            // k index: h*64+g
    int h = row >> 6;
    int tid = threadIdx.x;          // n index = c (256)
    __shared__ float osr[64];
    if (tid < 64) osr[tid] = g_os[(b*8 + h) * 4096 + (row & 63) * 64 + tid];
    __syncthreads();
    float s = 0.f;
    #pragma unroll 16
    for (int d = 0; d < 64; d++)
        s += osr[d] * Wout[(h*64 + d) * CC + tid];
    __nv_bfloat16 sh = __float2bfloat16(s);
    size_t idx = (size_t)b * (CC*INNER) + (size_t)tid * INNER + row;
    g_weffT_hi[idx] = sh;
    g_weffT_lo[idx] = __float2bfloat16(s - __bfloat162float(sh));
}

// ---------------- output GEMM (mma.sync): y = w @ W_eff[b] + b_out ----------------
// block M128 x N128, K=512 x 3 segments (24 chunks). grid (2, 1024): ct fast-varying.
__global__ __launch_bounds__(256, 2) void k_out(const float* __restrict__ bout,
                                                float* __restrict__ y) {
    extern __shared__ char sm[];
    float* stage = (float*)sm;
    uint32_t sb = smem_u32(sm);
    int tid = threadIdx.x;
    int lane = tid & 31, w = tid >> 5;
    int wm = w & 1, wn = w >> 1;
    int tileM = blockIdx.y, ct = blockIdx.x;
    int row0 = tileM * 128;
    int b = tileM >> 8;

    float acc[4][4][4];
    #pragma unroll
    for (int a = 0; a < 4; a++)
        #pragma unroll
        for (int bb2 = 0; bb2 < 4; bb2++)
            #pragma unroll
            for (int d = 0; d < 4; d++) acc[a][bb2][d] = 0.f;

    auto issue = [&](int c) {
        int p = c % 3, seg = c >> 3, k0 = (c & 7) * 64;
        const __nv_bfloat16* As = (seg == 2) ? g_w_lo : g_w_hi;
        const __nv_bfloat16* Bs = (seg == 1) ? g_weffT_lo : g_weffT_hi;
        #pragma unroll
        for (int i = 0; i < 4; i++) {
            int id = tid + i * 256, r = id >> 3, c8 = (id & 7) * 8;
            cpa16(sb + p*32768 + SWZ((uint32_t)(r*128 + c8*2)),
                  As + (size_t)(row0 + r) * INNER + k0 + c8);
        }
        #pragma unroll
        for (int i = 0; i < 4; i++) {
            int id = tid + i * 256, r = id >> 3, c8 = (id & 7) * 8;
            cpa16(sb + p*32768 + 16384 + SWZ((uint32_t)(r*128 + c8*2)),
                  Bs + (size_t)b * (CC*INNER) + (size_t)(ct*128 + r) * INNER + k0 + c8);
        }
        CP_COMMIT();
    };

    issue(0); issue(1);
    for (int c = 0; c < 24; c++) {
        if (c + 1 < 24) CP_WAIT1(); else CP_WAIT0();
        __syncthreads();
        uint32_t ab = sb + (c % 3) * 32768;
        uint32_t bbs = ab + 16384;
        int rA = lane & 15;
        #pragma unroll
        for (int kk = 0; kk < 4; kk++) {
            uint32_t af[4][4], bf[2][4];
            int kc = kk * 16 + (lane >> 4) * 8;
            #pragma unroll
            for (int mi = 0; mi < 4; mi++)
                ldsm4(af[mi], ab + SWZ((uint32_t)((wm*64 + mi*16 + rA)*128 + kc*2)));
            #pragma unroll
            for (int s = 0; s < 2; s++)
                ldsm4(bf[s], bbs + SWZ((uint32_t)((wn*32 + s*16 + rA)*128 + kc*2)));
            #pragma unroll
            for (int mi = 0; mi < 4; mi++)
                #pragma unroll
                for (int nj = 0; nj < 4; nj++)
                    mma_bf16(acc[mi][nj], af[mi][0], af[mi][1], af[mi][2], af[mi][3],
                             bf[nj>>1][nj&1], bf[nj>>1][(nj&1)+2]);
        }
        if (c + 2 < 24) issue(c + 2);
    }
    __syncthreads();

    #pragma unroll
    for (int mi = 0; mi < 4; mi++)
        #pragma unroll
        for (int nj = 0; nj < 4; nj++) {
            int row = wm*64 + mi*16 + (lane >> 2);
            int col = wn*32 + nj*8 + (lane & 3)*2;
            *(float2*)&stage[row*STG + col]     = make_float2(acc[mi][nj][0], acc[mi][nj][1]);
            *(float2*)&stage[(row+8)*STG + col] = make_float2(acc[mi][nj][2], acc[mi][nj][3]);
        }
    __syncthreads();
    #pragma unroll
    for (int i = 0; i < 16; i++) {
        int lin = tid + i * 256, r = lin >> 5, c4 = (lin & 31) * 4;
        float4 v = *(float4*)&stage[r*STG + c4];
        float4 bv = *(const float4*)&bout[ct*128 + c4];
        v.x += bv.x; v.y += bv.y; v.z += bv.z; v.w += bv.w;
        *(float4*)&y[(size_t)(row0 + r)*CC + ct*128 + c4] = v;
    }
}

// ---------------- launch ----------------
extern "C" void kernel_launch(void* const* d_in, const int* in_sizes, int n_in,
                              void* d_out, int out_size) {
    const float* x    = (const float*)d_in[0];
    const float* Wfx  = (const float*)d_in[1];
    const float* bfx  = (const float*)d_in[2];
    const float* Wx   = (const float*)d_in[3];
    const float* bx   = (const float*)d_in[4];
    const float* Wsl  = (const float*)d_in[5];
    const float* bsl  = (const float*)d_in[6];
    const float* temp = (const float*)d_in[7];
    const float* Wq   = (const float*)d_in[8];
    const float* Wk   = (const float*)d_in[9];
    const float* Wv   = (const float*)d_in[10];
    const float* Wout = (const float*)d_in[11];
    const float* bout = (const float*)d_in[12];
    float* y = (float*)d_out;

    cudaFuncSetAttribute(k_proj,  cudaFuncAttributeMaxDynamicSharedMemorySize, GSMEM);
    cudaFuncSetAttribute(k_poolg, cudaFuncAttributeMaxDynamicSharedMemorySize, PGSMEM);
    cudaFuncSetAttribute(k_out,   cudaFuncAttributeMaxDynamicSharedMemorySize, GSMEM);

    k_zero<<<2048, 256>>>();
    k_prep<<<CC, 512>>>(Wx, bx, Wsl, bsl);
    k_split<<<dim3(TOK/64, 4), 256>>>(x);
    k_proj<<<dim3(4, TOK/128), 256, GSMEM>>>(temp);
    k_poolg<<<dim3(32, 16, 2), 256, PGSMEM>>>();
    k_stok<<<32, 256>>>(Wfx, bfx);
    k_attn<<<32, 256>>>(Wq, Wk, Wv);
    k_weff<<<2048, 256>>>(Wout);
    k_out<<<dim3(2, TOK/128), 256, GSMEM>>>(bout, y);
}